// round 11
// baseline (speedup 1.0000x reference)
#include <cuda_runtime.h>
#include <math.h>

// ---------------- folded-weight scratch (device globals) -------------------
__device__ float g_Wqk0[19 * 32];
__device__ float g_WG1[36 * 32];
__device__ float g_bG1[32];
__device__ float g_Wout[36 * 4];
__device__ float g_bout[4];

#define QK_SCALE 0.17677669529663687f   // 1/sqrt(32)

// ---------------- packed f32x2 helpers --------------------------------------
struct f2 { unsigned long long v; };

__device__ __forceinline__ f2 mkf2(float lo, float hi) {
    f2 r; asm("mov.b64 %0,{%1,%2};" : "=l"(r.v) : "f"(lo), "f"(hi)); return r;
}
__device__ __forceinline__ void unf2(f2 a, float& lo, float& hi) {
    asm("mov.b64 {%0,%1},%2;" : "=f"(lo), "=f"(hi) : "l"(a.v));
}
__device__ __forceinline__ float f2lo(f2 a) { float l, h; unf2(a, l, h); return l; }
__device__ __forceinline__ float f2hi(f2 a) { float l, h; unf2(a, l, h); return h; }
__device__ __forceinline__ f2 dup(float x) { return mkf2(x, x); }
__device__ __forceinline__ f2 ffma2(f2 a, f2 b, f2 c) {
    f2 r; asm("fma.rn.f32x2 %0,%1,%2,%3;" : "=l"(r.v) : "l"(a.v), "l"(b.v), "l"(c.v)); return r;
}
__device__ __forceinline__ float sigf(float d) {   // 1/(1+exp(-d))
    float e = __expf(-d);
    float r;
    asm("rcp.approx.f32 %0,%1;" : "=f"(r) : "f"(1.f + e));
    return r;
}

// ---------------- single precompute kernel (unchanged) -----------------------
__global__ void __launch_bounds__(512, 1)
pk(const float* __restrict__ wq0,  const float* __restrict__ wak0,
   const float* __restrict__ wok0,
   const float* __restrict__ wq1,  const float* __restrict__ wak1,
   const float* __restrict__ wok1,
   const float* __restrict__ wav0, const float* __restrict__ apw0,
   const float* __restrict__ wov0, const float* __restrict__ opw0,
   const float* __restrict__ wav1, const float* __restrict__ apw1,
   const float* __restrict__ wov1, const float* __restrict__ opw1,
   const float* __restrict__ fpw0, const float* __restrict__ fpw1,
   const float* __restrict__ fpb0, const float* __restrict__ apb0,
   const float* __restrict__ opb0,
   const float* __restrict__ fpb1, const float* __restrict__ apb1,
   const float* __restrict__ opb1,
   const float* __restrict__ headw, const float* __restrict__ headb)
{
    __shared__ float sh[512];
    __shared__ float svec[128], sT[128], sW[128];
    __shared__ float sX[512];
    int bid = blockIdx.x, tid = threadIdx.x;

    if (bid < 19) {
        int p = bid;
        int t = tid >> 4, ci = tid & 15, h = t & 3;
        const float* wk; int j;
        if (t < 24) { wk = wak0; j = t >> 2; } else { wk = wok0; j = (t - 24) >> 2; }
        const float4* a4 = (const float4*)(wq0 + p * 512 + h * 128 + ci * 8);
        const float4* b4 = (const float4*)(wk + j * 512 + h * 128 + ci * 8);
        float4 a0 = a4[0], a1 = a4[1], b0 = b4[0], b1 = b4[1];
        float s = a0.x * b0.x + a0.y * b0.y + a0.z * b0.z + a0.w * b0.w
                + a1.x * b1.x + a1.y * b1.y + a1.z * b1.z + a1.w * b1.w;
#pragma unroll
        for (int off = 8; off; off >>= 1) s += __shfl_xor_sync(0xffffffffu, s, off);
        if (ci == 0) g_Wqk0[p * 32 + t] = s * QK_SCALE;
    } else if (bid < 91) {
        bool isW1 = (bid < 55);
        int t = isW1 ? bid - 19 : bid - 55;
        int h = t & 3;
        const float* wv; const float* pw; int j;
        if (isW1) {
            if (t < 28) { wv = wav0; pw = apw0; j = t >> 2; }
            else        { wv = wov0; pw = opw0; j = (t - 28) >> 2; }
        } else {
            if (t < 28) { wv = wav1; pw = apw1; j = t >> 2; }
            else        { wv = wov1; pw = opw1; j = (t - 28) >> 2; }
        }
        const float* fpw = isW1 ? fpw0 : fpw1;
        int q = tid >> 7, m = tid & 127;

        float pwv[32], fv[32];
        const float* baseT = pw + h * 16384 + q * 4096 + m;
        const float* baseW = fpw + (t < 28 ? 0 : 16384) + q * 4096 + m;
#pragma unroll
        for (int i = 0; i < 32; i++) pwv[i] = __ldg(baseT + i * 128);
#pragma unroll
        for (int i = 0; i < 32; i++) fv[i] = __ldg(baseW + i * 128);
        float4 hw = make_float4(0.f, 0.f, 0.f, 0.f);
        if (!isW1 && tid < 128) hw = *(const float4*)(headw + tid * 4);
        if (tid < 128) svec[tid] = wv[j * 512 + h * 128 + tid];
        __syncthreads();

        float s = 0.f;
#pragma unroll
        for (int i = 0; i < 32; i++) s += svec[q * 32 + i] * pwv[i];
        sh[tid] = s;
        __syncthreads();
        if (tid < 128)
            sT[tid] = (sh[tid] + sh[tid + 128]) + (sh[tid + 256] + sh[tid + 384]);
        __syncthreads();

        s = 0.f;
#pragma unroll
        for (int i = 0; i < 32; i++) s += sT[q * 32 + i] * fv[i];
        sh[tid] = s;
        __syncthreads();
        if (tid < 128)
            sW[tid] = (sh[tid] + sh[tid + 128]) + (sh[tid + 256] + sh[tid + 384]);
        __syncthreads();

        if (isW1) {
            float xa[4] = {0.f, 0.f, 0.f, 0.f};
            const float* wqc = wq1 + tid;
#pragma unroll 32
            for (int mm = 0; mm < 128; mm++)
                xa[mm & 3] += sW[mm] * __ldg(wqc + mm * 512);
            sX[tid] = (xa[0] + xa[1]) + (xa[2] + xa[3]);
            __syncthreads();
            int t2 = tid >> 4, ci = tid & 15, h2 = t2 & 3;
            const float* wk; int j2;
            if (t2 < 24) { wk = wak1; j2 = t2 >> 2; } else { wk = wok1; j2 = (t2 - 24) >> 2; }
            const float4* w4 = (const float4*)(wk + j2 * 512 + h2 * 128 + ci * 8);
            float4 wa = w4[0], wb = w4[1];
            const float* xs = sX + h2 * 128 + ci * 8;
            float s2 = xs[0] * wa.x + xs[1] * wa.y + xs[2] * wa.z + xs[3] * wa.w
                     + xs[4] * wb.x + xs[5] * wb.y + xs[6] * wb.z + xs[7] * wb.w;
#pragma unroll
            for (int off = 8; off; off >>= 1) s2 += __shfl_xor_sync(0xffffffffu, s2, off);
            if (ci == 0) g_WG1[t * 32 + t2] = s2 * QK_SCALE;
        } else {
            if (tid < 128) {
                float w0 = sW[tid];
                sh[tid]       = w0 * hw.x;
                sh[tid + 128] = w0 * hw.y;
                sh[tid + 256] = w0 * hw.z;
                sh[tid + 384] = w0 * hw.w;
            }
            __syncthreads();
            int w = tid >> 5, lane = tid & 31;
            if (w < 4) {
                float s2 = sh[w * 128 + lane] + sh[w * 128 + lane + 32]
                         + sh[w * 128 + lane + 64] + sh[w * 128 + lane + 96];
#pragma unroll
                for (int off = 16; off; off >>= 1) s2 += __shfl_xor_sync(0xffffffffu, s2, off);
                if (lane == 0) g_Wout[t * 4 + w] = s2;
            }
        }
    } else if (bid == 91) {
        int q = tid >> 7, m = tid & 127;
        float fa[32], fo[32];
        const float* basea = fpw0 + q * 4096 + m;
        const float* baseo = fpw0 + 16384 + q * 4096 + m;
#pragma unroll
        for (int i = 0; i < 32; i++) fa[i] = __ldg(basea + i * 128);
#pragma unroll
        for (int i = 0; i < 32; i++) fo[i] = __ldg(baseo + i * 128);
        float s = 0.f;
#pragma unroll
        for (int i = 0; i < 32; i++) {
            int m1 = q * 32 + i;
            s += apb0[m1] * fa[i] + opb0[m1] * fo[i];
        }
        sh[tid] = s;
        __syncthreads();
        if (tid < 128)
            sW[tid] = fpb0[tid] + (sh[tid] + sh[tid + 128]) + (sh[tid + 256] + sh[tid + 384]);
        __syncthreads();
        float xa[4] = {0.f, 0.f, 0.f, 0.f};
        const float* wqc = wq1 + tid;
#pragma unroll 32
        for (int mm = 0; mm < 128; mm++)
            xa[mm & 3] += sW[mm] * __ldg(wqc + mm * 512);
        sX[tid] = (xa[0] + xa[1]) + (xa[2] + xa[3]);
        __syncthreads();
        int t2 = tid >> 4, ci = tid & 15, h2 = t2 & 3;
        const float* wk; int j2;
        if (t2 < 24) { wk = wak1; j2 = t2 >> 2; } else { wk = wok1; j2 = (t2 - 24) >> 2; }
        const float4* w4 = (const float4*)(wk + j2 * 512 + h2 * 128 + ci * 8);
        float4 wa = w4[0], wb = w4[1];
        const float* xs = sX + h2 * 128 + ci * 8;
        float s2 = xs[0] * wa.x + xs[1] * wa.y + xs[2] * wa.z + xs[3] * wa.w
                 + xs[4] * wb.x + xs[5] * wb.y + xs[6] * wb.z + xs[7] * wb.w;
#pragma unroll
        for (int off = 8; off; off >>= 1) s2 += __shfl_xor_sync(0xffffffffu, s2, off);
        if (ci == 0) g_bG1[t2] = s2 * QK_SCALE;
    } else {
        int q = tid >> 7, m = tid & 127;
        float fa[32], fo[32];
        const float* basea = fpw1 + q * 4096 + m;
        const float* baseo = fpw1 + 16384 + q * 4096 + m;
#pragma unroll
        for (int i = 0; i < 32; i++) fa[i] = __ldg(basea + i * 128);
#pragma unroll
        for (int i = 0; i < 32; i++) fo[i] = __ldg(baseo + i * 128);
        float4 hw = make_float4(0.f, 0.f, 0.f, 0.f);
        if (tid < 128) hw = *(const float4*)(headw + tid * 4);
        float s = 0.f;
#pragma unroll
        for (int i = 0; i < 32; i++) {
            int m1 = q * 32 + i;
            s += apb1[m1] * fa[i] + opb1[m1] * fo[i];
        }
        sh[tid] = s;
        __syncthreads();
        if (tid < 128)
            sW[tid] = fpb1[tid] + (sh[tid] + sh[tid + 128]) + (sh[tid + 256] + sh[tid + 384]);
        __syncthreads();
        if (tid < 128) {
            float b = sW[tid];
            sh[tid]       = b * hw.x;
            sh[tid + 128] = b * hw.y;
            sh[tid + 256] = b * hw.z;
            sh[tid + 384] = b * hw.w;
        }
        __syncthreads();
        int w = tid >> 5, lane = tid & 31;
        if (w < 4) {
            float s2 = sh[w * 128 + lane] + sh[w * 128 + lane + 32]
                     + sh[w * 128 + lane + 64] + sh[w * 128 + lane + 96];
#pragma unroll
            for (int off = 16; off; off >>= 1) s2 += __shfl_xor_sync(0xffffffffu, s2, off);
            if (lane == 0) g_bout[w] = headb[w] + s2;
        }
    }
}

// ---------------- main kernel: 1 row/thread, output-paired f32x2 --------------
struct Row {
    float nbv[2][7];
    float dnbv[7];
    float obf[2][2];
    float dobf[2];
};

template <int W, int PASSES>
__device__ __forceinline__ void attend1(
    const f2 (&G)[16],
    const float (&dwA)[2], const float (&dwO)[2],
    const Row& r,
    const float* __restrict__ wtab, const float* __restrict__ bias,
    f2* OUT)
{
#define GET(t) (((t) & 1) ? f2hi(G[(t) >> 1]) : f2lo(G[(t) >> 1]))
    float sA[4], sO[4];
#pragma unroll
    for (int h = 0; h < 4; h++) {
        float d0 = 0.f, d1 = 0.f;
#pragma unroll
        for (int j = 0; j < 6; j++) {
            float g = GET(j * 4 + h);
            d0 = fmaf(r.nbv[0][j], g, d0);
            d1 = fmaf(r.nbv[1][j], g, d1);
        }
        sA[h] = sigf(d0 * dwA[0] - d1 * dwA[1]);
        float g24 = GET(24 + h), g28 = GET(28 + h);
        float e0 = r.obf[0][0] * g24 + r.obf[0][1] * g28;
        float e1 = r.obf[1][0] * g24 + r.obf[1][1] * g28;
        sO[h] = sigf(e0 * dwO[0] - e1 * dwO[1]);
    }
#undef GET

    constexpr int PW = W / PASSES;   // outputs per pass
    constexpr int PP = PW / 2;       // f2 pairs per pass
#pragma unroll
    for (int pass = 0; pass < PASSES; pass++) {
        f2 ACC[PP];
#pragma unroll
        for (int i = 0; i < PP; i++)
            ACC[i] = *(const f2*)&bias[pass * PW + 2 * i];
#pragma unroll
        for (int h = 0; h < 4; h++) {
#pragma unroll
            for (int j = 0; j < 9; j++) {
                float u; int tu;
                if (j < 7) {
                    u = fmaf(sA[h], r.dnbv[j], r.nbv[1][j]);
                    tu = j * 4 + h;
                } else {
                    int jo = j - 7;
                    u = fmaf(sO[h], r.dobf[jo], r.obf[1][jo]);
                    tu = 28 + jo * 4 + h;
                }
                f2 uv = dup(u);
                const float4* row = (const float4*)&wtab[tu * W + pass * PW];
#pragma unroll
                for (int i = 0; i < PP / 2; i++) {
                    float4 w = row[i];               // one LDS.128 = 4 unique weights
                    ACC[2 * i]     = ffma2(uv, mkf2(w.x, w.y), ACC[2 * i]);
                    ACC[2 * i + 1] = ffma2(uv, mkf2(w.z, w.w), ACC[2 * i + 1]);
                }
            }
        }
#pragma unroll
        for (int i = 0; i < PP; i++) OUT[pass * PP + i] = ACC[i];
    }
}

// smem layout (128 rows/block, 128 threads, 1 row/thread, 5 blocks/SM)
#define MT           128
#define MROWS        128
#define SM_OBS_F     (MROWS * 37)
#define SM_OBS_B     (SM_OBS_F * 4)                 // 18944
#define SM_WQK0_OFF  SM_OBS_B                       // 608 floats
#define SM_WG1_OFF   (SM_WQK0_OFF + 608 * 4)        // 1152 floats
#define SM_WOUT_OFF  (SM_WG1_OFF + 1152 * 4)        // 144 floats
#define SM_BG1_OFF   (SM_WOUT_OFF + 144 * 4)        // 32 floats
#define SM_BOUT_OFF  (SM_BG1_OFF + 32 * 4)          // 4 floats
#define SM_TOTAL     (SM_BOUT_OFF + 4 * 4)          // 26704 B

__global__ void __launch_bounds__(MT, 5)
actor_main(const float* __restrict__ obs,
           const float* __restrict__ ca0p, const float* __restrict__ co0p,
           const float* __restrict__ ca1p, const float* __restrict__ co1p,
           float* __restrict__ out, int n)
{
    extern __shared__ __align__(16) unsigned char smbuf[];
    float* sObs  = (float*)smbuf;
    float* sWqk0 = (float*)(smbuf + SM_WQK0_OFF);
    float* sWG1  = (float*)(smbuf + SM_WG1_OFF);
    float* sWout = (float*)(smbuf + SM_WOUT_OFF);
    float* sbG1  = (float*)(smbuf + SM_BG1_OFF);
    float* sbout = (float*)(smbuf + SM_BOUT_OFF);

    int tid = threadIdx.x;

    // ---- stage obs (independent of pk; overlaps it via PDL) ----
    {
        long nel = (long)n * 37;
        long eb  = (long)blockIdx.x * SM_OBS_F;
        const float4* g4 = (const float4*)obs;
        float4* s4 = (float4*)sObs;
#pragma unroll 4
        for (int i = tid; i < SM_OBS_F / 4; i += MT) {
            long e = eb + (long)i * 4;
            if (e + 3 < nel) {
                s4[i] = g4[eb / 4 + i];
            } else {
#pragma unroll
                for (int k = 0; k < 4; k++)
                    sObs[i * 4 + k] = (e + k < nel) ? obs[e + k] : 0.f;
            }
        }
    }

    cudaGridDependencySynchronize();

    for (int i = tid; i < 608;  i += MT) sWqk0[i] = g_Wqk0[i];
    for (int i = tid; i < 1152; i += MT) sWG1[i]  = g_WG1[i];
    for (int i = tid; i < 144;  i += MT) sWout[i] = g_Wout[i];
    if (tid < 32) sbG1[tid] = g_bG1[tid];
    if (tid < 4)  sbout[tid] = g_bout[tid];
    __syncthreads();

    int r0 = blockIdx.x * MROWS + tid;
    if (r0 >= n) return;
    const float* lo = &sObs[tid * 37];

    // ---- scalar per-row features ----
    Row rl;
#pragma unroll
    for (int k = 0; k < 2; k++) {
#pragma unroll
        for (int j = 0; j < 6; j++) rl.nbv[k][j] = lo[12 + 6 * k + j];
        rl.nbv[k][6] = lo[24 + k];
        rl.obf[k][0] = lo[26 + 2 * k];
        rl.obf[k][1] = lo[27 + 2 * k];
    }
#pragma unroll
    for (int j = 0; j < 7; j++) rl.dnbv[j] = rl.nbv[0][j] - rl.nbv[1][j];
#pragma unroll
    for (int j = 0; j < 2; j++) rl.dobf[j] = rl.obf[0][j] - rl.obf[1][j];

    // ---- distances (shared by both layers) ----
    float dA[2], dO[2];
    {
        float ax = lo[0], ay = lo[1];
#pragma unroll
        for (int k = 0; k < 2; k++) {
            float dx = ax - rl.nbv[k][0], dy = ay - rl.nbv[k][1];
            dA[k] = sqrtf(dx * dx + dy * dy);
            dx = ax - rl.obf[k][0]; dy = ay - rl.obf[k][1];
            dO[k] = sqrtf(dx * dx + dy * dy);
        }
    }

    // ---- layer-0 logit features: G = qf @ Wqk0 (output-pair layout) ----
    f2 G[16];
#pragma unroll
    for (int t = 0; t < 16; t++) G[t] = f2{0ull};
#pragma unroll
    for (int p = 0; p < 19; p++) {
        int src = (p < 12) ? p : p + 18;
        f2 qd = dup(lo[src]);
        const float4* w4 = (const float4*)&sWqk0[p * 32];
#pragma unroll
        for (int i = 0; i < 8; i++) {
            float4 w = w4[i];
            G[2 * i]     = ffma2(qd, mkf2(w.x, w.y), G[2 * i]);
            G[2 * i + 1] = ffma2(qd, mkf2(w.z, w.w), G[2 * i + 1]);
        }
    }

    // ---- layer 0 -> G1 ----
    f2 G1[16];
    {
        float nca0 = -__ldg(ca0p), nco0 = -__ldg(co0p);
        float dwA[2] = { __expf(nca0 * dA[0]), __expf(nca0 * dA[1]) };
        float dwO[2] = { __expf(nco0 * dO[0]), __expf(nco0 * dO[1]) };
        attend1<32, 2>(G, dwA, dwO, rl, sWG1, sbG1, G1);
    }

    // ---- layer 1 -> output ----
    f2 R[2];
    {
        float nca1 = -__ldg(ca1p), nco1 = -__ldg(co1p);
        float dwA[2] = { __expf(nca1 * dA[0]), __expf(nca1 * dA[1]) };
        float dwO[2] = { __expf(nco1 * dO[0]), __expf(nco1 * dO[1]) };
        attend1<4, 1>(G1, dwA, dwO, rl, sWout, sbout, R);
    }

    ((float4*)out)[r0] = make_float4(f2lo(R[0]), f2hi(R[0]), f2lo(R[1]), f2hi(R[1]));
}

// ---------------- launch -----------------------------------------------------
extern "C" void kernel_launch(void* const* d_in, const int* in_sizes, int n_in,
                              void* d_out, int out_size)
{
    const float* obs   = (const float*)d_in[0];
    const float* wq0   = (const float*)d_in[1];
    const float* wak0  = (const float*)d_in[2];
    const float* wav0  = (const float*)d_in[3];
    const float* wok0  = (const float*)d_in[4];
    const float* wov0  = (const float*)d_in[5];
    const float* apw0  = (const float*)d_in[6];
    const float* apb0  = (const float*)d_in[7];
    const float* opw0  = (const float*)d_in[8];
    const float* opb0  = (const float*)d_in[9];
    const float* fpw0  = (const float*)d_in[10];
    const float* fpb0  = (const float*)d_in[11];
    const float* ca0   = (const float*)d_in[12];
    const float* co0   = (const float*)d_in[13];
    const float* wq1   = (const float*)d_in[14];
    const float* wak1  = (const float*)d_in[15];
    const float* wav1  = (const float*)d_in[16];
    const float* wok1  = (const float*)d_in[17];
    const float* wov1  = (const float*)d_in[18];
    const float* apw1  = (const float*)d_in[19];
    const float* apb1  = (const float*)d_in[20];
    const float* opw1  = (const float*)d_in[21];
    const float* opb1  = (const float*)d_in[22];
    const float* fpw1  = (const float*)d_in[23];
    const float* fpb1  = (const float*)d_in[24];
    const float* ca1   = (const float*)d_in[25];
    const float* co1   = (const float*)d_in[26];
    const float* headw = (const float*)d_in[27];
    const float* headb = (const float*)d_in[28];

    int n = in_sizes[0] / 37;

    pk<<<93, 512>>>(wq0, wak0, wok0, wq1, wak1, wok1,
                    wav0, apw0, wov0, opw0, wav1, apw1, wov1, opw1,
                    fpw0, fpw1, fpb0, apb0, opb0, fpb1, apb1, opb1,
                    headw, headb);

    cudaFuncSetAttribute(actor_main, cudaFuncAttributeMaxDynamicSharedMemorySize, SM_TOTAL);

    int grid = (n + MROWS - 1) / MROWS;

    cudaLaunchConfig_t cfg = {};
    cfg.gridDim  = dim3((unsigned)grid, 1, 1);
    cfg.blockDim = dim3(MT, 1, 1);
    cfg.dynamicSmemBytes = SM_TOTAL;
    cfg.stream = 0;
    cudaLaunchAttribute attrs[1];
    attrs[0].id = cudaLaunchAttributeProgrammaticStreamSerialization;
    attrs[0].val.programmaticStreamSerializationAllowed = 1;
    cfg.attrs = attrs;
    cfg.numAttrs = 1;

    cudaLaunchKernelEx(&cfg, actor_main, obs, ca0, co0, ca1, co1, (float*)d_out, n);
}

// round 12
// speedup vs baseline: 1.1311x; 1.1311x over previous
#include <cuda_runtime.h>
#include <math.h>

// ---------------- folded-weight scratch (device globals) -------------------
__device__ float g_Wqk0[19 * 32];
__device__ float g_WG1[36 * 32];
__device__ float g_bG1[32];
__device__ float g_Wout[36 * 4];
__device__ float g_bout[4];

#define QK_SCALE 0.17677669529663687f   // 1/sqrt(32)

// ---------------- packed f32x2 helpers --------------------------------------
struct f2 { unsigned long long v; };

__device__ __forceinline__ f2 mkf2(float lo, float hi) {
    f2 r; asm("mov.b64 %0,{%1,%2};" : "=l"(r.v) : "f"(lo), "f"(hi)); return r;
}
__device__ __forceinline__ void unf2(f2 a, float& lo, float& hi) {
    asm("mov.b64 {%0,%1},%2;" : "=f"(lo), "=f"(hi) : "l"(a.v));
}
__device__ __forceinline__ float f2lo(f2 a) { float l, h; unf2(a, l, h); return l; }
__device__ __forceinline__ float f2hi(f2 a) { float l, h; unf2(a, l, h); return h; }
__device__ __forceinline__ f2 dup(float x) { return mkf2(x, x); }
__device__ __forceinline__ f2 ffma2(f2 a, f2 b, f2 c) {
    f2 r; asm("fma.rn.f32x2 %0,%1,%2,%3;" : "=l"(r.v) : "l"(a.v), "l"(b.v), "l"(c.v)); return r;
}
__device__ __forceinline__ float sigf(float d) {   // 1/(1+exp(-d))
    float e = __expf(-d);
    float r;
    asm("rcp.approx.f32 %0,%1;" : "=f"(r) : "f"(1.f + e));
    return r;
}

// ---------------- single precompute kernel (unchanged) -----------------------
__global__ void __launch_bounds__(512, 1)
pk(const float* __restrict__ wq0,  const float* __restrict__ wak0,
   const float* __restrict__ wok0,
   const float* __restrict__ wq1,  const float* __restrict__ wak1,
   const float* __restrict__ wok1,
   const float* __restrict__ wav0, const float* __restrict__ apw0,
   const float* __restrict__ wov0, const float* __restrict__ opw0,
   const float* __restrict__ wav1, const float* __restrict__ apw1,
   const float* __restrict__ wov1, const float* __restrict__ opw1,
   const float* __restrict__ fpw0, const float* __restrict__ fpw1,
   const float* __restrict__ fpb0, const float* __restrict__ apb0,
   const float* __restrict__ opb0,
   const float* __restrict__ fpb1, const float* __restrict__ apb1,
   const float* __restrict__ opb1,
   const float* __restrict__ headw, const float* __restrict__ headb)
{
    __shared__ float sh[512];
    __shared__ float svec[128], sT[128], sW[128];
    __shared__ float sX[512];
    int bid = blockIdx.x, tid = threadIdx.x;

    if (bid < 19) {
        int p = bid;
        int t = tid >> 4, ci = tid & 15, h = t & 3;
        const float* wk; int j;
        if (t < 24) { wk = wak0; j = t >> 2; } else { wk = wok0; j = (t - 24) >> 2; }
        const float4* a4 = (const float4*)(wq0 + p * 512 + h * 128 + ci * 8);
        const float4* b4 = (const float4*)(wk + j * 512 + h * 128 + ci * 8);
        float4 a0 = a4[0], a1 = a4[1], b0 = b4[0], b1 = b4[1];
        float s = a0.x * b0.x + a0.y * b0.y + a0.z * b0.z + a0.w * b0.w
                + a1.x * b1.x + a1.y * b1.y + a1.z * b1.z + a1.w * b1.w;
#pragma unroll
        for (int off = 8; off; off >>= 1) s += __shfl_xor_sync(0xffffffffu, s, off);
        if (ci == 0) g_Wqk0[p * 32 + t] = s * QK_SCALE;
    } else if (bid < 91) {
        bool isW1 = (bid < 55);
        int t = isW1 ? bid - 19 : bid - 55;
        int h = t & 3;
        const float* wv; const float* pw; int j;
        if (isW1) {
            if (t < 28) { wv = wav0; pw = apw0; j = t >> 2; }
            else        { wv = wov0; pw = opw0; j = (t - 28) >> 2; }
        } else {
            if (t < 28) { wv = wav1; pw = apw1; j = t >> 2; }
            else        { wv = wov1; pw = opw1; j = (t - 28) >> 2; }
        }
        const float* fpw = isW1 ? fpw0 : fpw1;
        int q = tid >> 7, m = tid & 127;

        float pwv[32], fv[32];
        const float* baseT = pw + h * 16384 + q * 4096 + m;
        const float* baseW = fpw + (t < 28 ? 0 : 16384) + q * 4096 + m;
#pragma unroll
        for (int i = 0; i < 32; i++) pwv[i] = __ldg(baseT + i * 128);
#pragma unroll
        for (int i = 0; i < 32; i++) fv[i] = __ldg(baseW + i * 128);
        float4 hw = make_float4(0.f, 0.f, 0.f, 0.f);
        if (!isW1 && tid < 128) hw = *(const float4*)(headw + tid * 4);
        if (tid < 128) svec[tid] = wv[j * 512 + h * 128 + tid];
        __syncthreads();

        float s = 0.f;
#pragma unroll
        for (int i = 0; i < 32; i++) s += svec[q * 32 + i] * pwv[i];
        sh[tid] = s;
        __syncthreads();
        if (tid < 128)
            sT[tid] = (sh[tid] + sh[tid + 128]) + (sh[tid + 256] + sh[tid + 384]);
        __syncthreads();

        s = 0.f;
#pragma unroll
        for (int i = 0; i < 32; i++) s += sT[q * 32 + i] * fv[i];
        sh[tid] = s;
        __syncthreads();
        if (tid < 128)
            sW[tid] = (sh[tid] + sh[tid + 128]) + (sh[tid + 256] + sh[tid + 384]);
        __syncthreads();

        if (isW1) {
            float xa[4] = {0.f, 0.f, 0.f, 0.f};
            const float* wqc = wq1 + tid;
#pragma unroll 32
            for (int mm = 0; mm < 128; mm++)
                xa[mm & 3] += sW[mm] * __ldg(wqc + mm * 512);
            sX[tid] = (xa[0] + xa[1]) + (xa[2] + xa[3]);
            __syncthreads();
            int t2 = tid >> 4, ci = tid & 15, h2 = t2 & 3;
            const float* wk; int j2;
            if (t2 < 24) { wk = wak1; j2 = t2 >> 2; } else { wk = wok1; j2 = (t2 - 24) >> 2; }
            const float4* w4 = (const float4*)(wk + j2 * 512 + h2 * 128 + ci * 8);
            float4 wa = w4[0], wb = w4[1];
            const float* xs = sX + h2 * 128 + ci * 8;
            float s2 = xs[0] * wa.x + xs[1] * wa.y + xs[2] * wa.z + xs[3] * wa.w
                     + xs[4] * wb.x + xs[5] * wb.y + xs[6] * wb.z + xs[7] * wb.w;
#pragma unroll
            for (int off = 8; off; off >>= 1) s2 += __shfl_xor_sync(0xffffffffu, s2, off);
            if (ci == 0) g_WG1[t * 32 + t2] = s2 * QK_SCALE;
        } else {
            if (tid < 128) {
                float w0 = sW[tid];
                sh[tid]       = w0 * hw.x;
                sh[tid + 128] = w0 * hw.y;
                sh[tid + 256] = w0 * hw.z;
                sh[tid + 384] = w0 * hw.w;
            }
            __syncthreads();
            int w = tid >> 5, lane = tid & 31;
            if (w < 4) {
                float s2 = sh[w * 128 + lane] + sh[w * 128 + lane + 32]
                         + sh[w * 128 + lane + 64] + sh[w * 128 + lane + 96];
#pragma unroll
                for (int off = 16; off; off >>= 1) s2 += __shfl_xor_sync(0xffffffffu, s2, off);
                if (lane == 0) g_Wout[t * 4 + w] = s2;
            }
        }
    } else if (bid == 91) {
        int q = tid >> 7, m = tid & 127;
        float fa[32], fo[32];
        const float* basea = fpw0 + q * 4096 + m;
        const float* baseo = fpw0 + 16384 + q * 4096 + m;
#pragma unroll
        for (int i = 0; i < 32; i++) fa[i] = __ldg(basea + i * 128);
#pragma unroll
        for (int i = 0; i < 32; i++) fo[i] = __ldg(baseo + i * 128);
        float s = 0.f;
#pragma unroll
        for (int i = 0; i < 32; i++) {
            int m1 = q * 32 + i;
            s += apb0[m1] * fa[i] + opb0[m1] * fo[i];
        }
        sh[tid] = s;
        __syncthreads();
        if (tid < 128)
            sW[tid] = fpb0[tid] + (sh[tid] + sh[tid + 128]) + (sh[tid + 256] + sh[tid + 384]);
        __syncthreads();
        float xa[4] = {0.f, 0.f, 0.f, 0.f};
        const float* wqc = wq1 + tid;
#pragma unroll 32
        for (int mm = 0; mm < 128; mm++)
            xa[mm & 3] += sW[mm] * __ldg(wqc + mm * 512);
        sX[tid] = (xa[0] + xa[1]) + (xa[2] + xa[3]);
        __syncthreads();
        int t2 = tid >> 4, ci = tid & 15, h2 = t2 & 3;
        const float* wk; int j2;
        if (t2 < 24) { wk = wak1; j2 = t2 >> 2; } else { wk = wok1; j2 = (t2 - 24) >> 2; }
        const float4* w4 = (const float4*)(wk + j2 * 512 + h2 * 128 + ci * 8);
        float4 wa = w4[0], wb = w4[1];
        const float* xs = sX + h2 * 128 + ci * 8;
        float s2 = xs[0] * wa.x + xs[1] * wa.y + xs[2] * wa.z + xs[3] * wa.w
                 + xs[4] * wb.x + xs[5] * wb.y + xs[6] * wb.z + xs[7] * wb.w;
#pragma unroll
        for (int off = 8; off; off >>= 1) s2 += __shfl_xor_sync(0xffffffffu, s2, off);
        if (ci == 0) g_bG1[t2] = s2 * QK_SCALE;
    } else {
        int q = tid >> 7, m = tid & 127;
        float fa[32], fo[32];
        const float* basea = fpw1 + q * 4096 + m;
        const float* baseo = fpw1 + 16384 + q * 4096 + m;
#pragma unroll
        for (int i = 0; i < 32; i++) fa[i] = __ldg(basea + i * 128);
#pragma unroll
        for (int i = 0; i < 32; i++) fo[i] = __ldg(baseo + i * 128);
        float4 hw = make_float4(0.f, 0.f, 0.f, 0.f);
        if (tid < 128) hw = *(const float4*)(headw + tid * 4);
        float s = 0.f;
#pragma unroll
        for (int i = 0; i < 32; i++) {
            int m1 = q * 32 + i;
            s += apb1[m1] * fa[i] + opb1[m1] * fo[i];
        }
        sh[tid] = s;
        __syncthreads();
        if (tid < 128)
            sW[tid] = fpb1[tid] + (sh[tid] + sh[tid + 128]) + (sh[tid + 256] + sh[tid + 384]);
        __syncthreads();
        if (tid < 128) {
            float b = sW[tid];
            sh[tid]       = b * hw.x;
            sh[tid + 128] = b * hw.y;
            sh[tid + 256] = b * hw.z;
            sh[tid + 384] = b * hw.w;
        }
        __syncthreads();
        int w = tid >> 5, lane = tid & 31;
        if (w < 4) {
            float s2 = sh[w * 128 + lane] + sh[w * 128 + lane + 32]
                     + sh[w * 128 + lane + 64] + sh[w * 128 + lane + 96];
#pragma unroll
            for (int off = 16; off; off >>= 1) s2 += __shfl_xor_sync(0xffffffffu, s2, off);
            if (lane == 0) g_bout[w] = headb[w] + s2;
        }
    }
}

// ---------------- main kernel: output-paired f32x2, non-duplicated weights ----
// 2 rows/thread (weight LDS amortized), 160 threads x 3 blocks/SM (15 warps).
struct Row {
    float nbv[2][7];
    float dnbv[7];
    float obf[2][2];
    float dobf[2];
};

template <int W, int PASSES>
__device__ __forceinline__ void attend2(
    const f2 (&GL)[16], const f2 (&GH)[16],
    const float (&dwAL)[2], const float (&dwAH)[2],
    const float (&dwOL)[2], const float (&dwOH)[2],
    const Row& rl, const Row& rh,
    const float* __restrict__ wtab, const float* __restrict__ bias,
    f2* OUTL, f2* OUTH)
{
#define GET(Gr, t) (((t) & 1) ? f2hi(Gr[(t) >> 1]) : f2lo(Gr[(t) >> 1]))
    float sAL[4], sAH[4], sOL[4], sOH[4];
#pragma unroll
    for (int h = 0; h < 4; h++) {
        float d0L = 0.f, d1L = 0.f, d0H = 0.f, d1H = 0.f;
#pragma unroll
        for (int j = 0; j < 6; j++) {
            float gl = GET(GL, j * 4 + h), gh = GET(GH, j * 4 + h);
            d0L = fmaf(rl.nbv[0][j], gl, d0L);
            d1L = fmaf(rl.nbv[1][j], gl, d1L);
            d0H = fmaf(rh.nbv[0][j], gh, d0H);
            d1H = fmaf(rh.nbv[1][j], gh, d1H);
        }
        sAL[h] = sigf(d0L * dwAL[0] - d1L * dwAL[1]);
        sAH[h] = sigf(d0H * dwAH[0] - d1H * dwAH[1]);
        float g24L = GET(GL, 24 + h), g28L = GET(GL, 28 + h);
        float g24H = GET(GH, 24 + h), g28H = GET(GH, 28 + h);
        float e0L = rl.obf[0][0] * g24L + rl.obf[0][1] * g28L;
        float e1L = rl.obf[1][0] * g24L + rl.obf[1][1] * g28L;
        float e0H = rh.obf[0][0] * g24H + rh.obf[0][1] * g28H;
        float e1H = rh.obf[1][0] * g24H + rh.obf[1][1] * g28H;
        sOL[h] = sigf(e0L * dwOL[0] - e1L * dwOL[1]);
        sOH[h] = sigf(e0H * dwOH[0] - e1H * dwOH[1]);
    }
#undef GET

    constexpr int PW = W / PASSES;   // outputs per pass
    constexpr int PP = PW / 2;       // f2 pairs per pass
#pragma unroll
    for (int pass = 0; pass < PASSES; pass++) {
        f2 AL[PP], AH[PP];
#pragma unroll
        for (int i = 0; i < PP; i++) {
            f2 b = *(const f2*)&bias[pass * PW + 2 * i];
            AL[i] = b; AH[i] = b;
        }
#pragma unroll
        for (int h = 0; h < 4; h++) {
#pragma unroll
            for (int j = 0; j < 9; j++) {
                float uL, uH; int tu;
                if (j < 7) {
                    uL = fmaf(sAL[h], rl.dnbv[j], rl.nbv[1][j]);
                    uH = fmaf(sAH[h], rh.dnbv[j], rh.nbv[1][j]);
                    tu = j * 4 + h;
                } else {
                    int jo = j - 7;
                    uL = fmaf(sOL[h], rl.dobf[jo], rl.obf[1][jo]);
                    uH = fmaf(sOH[h], rh.dobf[jo], rh.obf[1][jo]);
                    tu = 28 + jo * 4 + h;
                }
                f2 uvL = dup(uL), uvH = dup(uH);
                const float4* row = (const float4*)&wtab[tu * W + pass * PW];
#pragma unroll
                for (int i = 0; i < PP / 2; i++) {
                    float4 w = row[i];               // one LDS.128 = 4 unique weights
                    f2 w01 = mkf2(w.x, w.y);
                    f2 w23 = mkf2(w.z, w.w);
                    AL[2 * i]     = ffma2(uvL, w01, AL[2 * i]);
                    AL[2 * i + 1] = ffma2(uvL, w23, AL[2 * i + 1]);
                    AH[2 * i]     = ffma2(uvH, w01, AH[2 * i]);
                    AH[2 * i + 1] = ffma2(uvH, w23, AH[2 * i + 1]);
                }
            }
        }
#pragma unroll
        for (int i = 0; i < PP; i++) {
            OUTL[pass * PP + i] = AL[i];
            OUTH[pass * PP + i] = AH[i];
        }
    }
}

// smem layout (320 rows/block, 160 threads, 2 rows/thread, 3 blocks/SM)
#define MT           160
#define MROWS        320
#define SM_OBS_F     (MROWS * 37)                   // 11840 floats
#define SM_OBS_B     (SM_OBS_F * 4)                 // 47360 B
#define SM_WQK0_OFF  SM_OBS_B                       // 608 floats
#define SM_WG1_OFF   (SM_WQK0_OFF + 608 * 4)        // 1152 floats
#define SM_WOUT_OFF  (SM_WG1_OFF + 1152 * 4)        // 144 floats
#define SM_BG1_OFF   (SM_WOUT_OFF + 144 * 4)        // 32 floats
#define SM_BOUT_OFF  (SM_BG1_OFF + 32 * 4)          // 4 floats
#define SM_TOTAL     (SM_BOUT_OFF + 4 * 4)          // 55120 B  (x3 = 165KB < 228KB)

__global__ void __launch_bounds__(MT, 3)
actor_main(const float* __restrict__ obs,
           const float* __restrict__ ca0p, const float* __restrict__ co0p,
           const float* __restrict__ ca1p, const float* __restrict__ co1p,
           float* __restrict__ out, int n)
{
    extern __shared__ __align__(16) unsigned char smbuf[];
    float* sObs  = (float*)smbuf;
    float* sWqk0 = (float*)(smbuf + SM_WQK0_OFF);
    float* sWG1  = (float*)(smbuf + SM_WG1_OFF);
    float* sWout = (float*)(smbuf + SM_WOUT_OFF);
    float* sbG1  = (float*)(smbuf + SM_BG1_OFF);
    float* sbout = (float*)(smbuf + SM_BOUT_OFF);

    int tid = threadIdx.x;

    // ---- stage obs (independent of pk; overlaps it via PDL) ----
    {
        long nel = (long)n * 37;
        long eb  = (long)blockIdx.x * SM_OBS_F;
        const float4* g4 = (const float4*)obs;
        float4* s4 = (float4*)sObs;
#pragma unroll 4
        for (int i = tid; i < SM_OBS_F / 4; i += MT) {
            long e = eb + (long)i * 4;
            if (e + 3 < nel) {
                s4[i] = g4[eb / 4 + i];
            } else {
#pragma unroll
                for (int k = 0; k < 4; k++)
                    sObs[i * 4 + k] = (e + k < nel) ? obs[e + k] : 0.f;
            }
        }
    }

    cudaGridDependencySynchronize();

    for (int i = tid; i < 608;  i += MT) sWqk0[i] = g_Wqk0[i];
    for (int i = tid; i < 1152; i += MT) sWG1[i]  = g_WG1[i];
    if (tid < 144) sWout[tid] = g_Wout[tid];
    if (tid < 32) sbG1[tid] = g_bG1[tid];
    if (tid < 4)  sbout[tid] = g_bout[tid];
    __syncthreads();

    int r0 = blockIdx.x * MROWS + tid;
    if (r0 >= n) return;
    int r1 = r0 + MT;
    const float* lo = &sObs[tid * 37];
    const float* hi = &sObs[(tid + MT) * 37];

    // ---- scalar per-row features ----
    Row rl, rh;
#pragma unroll
    for (int k = 0; k < 2; k++) {
#pragma unroll
        for (int j = 0; j < 6; j++) {
            rl.nbv[k][j] = lo[12 + 6 * k + j];
            rh.nbv[k][j] = hi[12 + 6 * k + j];
        }
        rl.nbv[k][6] = lo[24 + k];
        rh.nbv[k][6] = hi[24 + k];
        rl.obf[k][0] = lo[26 + 2 * k]; rl.obf[k][1] = lo[27 + 2 * k];
        rh.obf[k][0] = hi[26 + 2 * k]; rh.obf[k][1] = hi[27 + 2 * k];
    }
#pragma unroll
    for (int j = 0; j < 7; j++) {
        rl.dnbv[j] = rl.nbv[0][j] - rl.nbv[1][j];
        rh.dnbv[j] = rh.nbv[0][j] - rh.nbv[1][j];
    }
#pragma unroll
    for (int j = 0; j < 2; j++) {
        rl.dobf[j] = rl.obf[0][j] - rl.obf[1][j];
        rh.dobf[j] = rh.obf[0][j] - rh.obf[1][j];
    }

    // ---- distances (shared by both layers) ----
    float dAl[2], dAh[2], dOl[2], dOh[2];
    {
        float axl = lo[0], ayl = lo[1], axh = hi[0], ayh = hi[1];
#pragma unroll
        for (int k = 0; k < 2; k++) {
            float dx = axl - rl.nbv[k][0], dy = ayl - rl.nbv[k][1];
            dAl[k] = sqrtf(dx * dx + dy * dy);
            dx = axh - rh.nbv[k][0]; dy = ayh - rh.nbv[k][1];
            dAh[k] = sqrtf(dx * dx + dy * dy);
            dx = axl - rl.obf[k][0]; dy = ayl - rl.obf[k][1];
            dOl[k] = sqrtf(dx * dx + dy * dy);
            dx = axh - rh.obf[k][0]; dy = ayh - rh.obf[k][1];
            dOh[k] = sqrtf(dx * dx + dy * dy);
        }
    }

    // ---- layer-0 logit features: G = qf @ Wqk0 (output-pair layout) ----
    f2 GL[16], GH[16];
#pragma unroll
    for (int t = 0; t < 16; t++) { GL[t] = f2{0ull}; GH[t] = f2{0ull}; }
#pragma unroll
    for (int p = 0; p < 19; p++) {
        int src = (p < 12) ? p : p + 18;
        f2 qdL = dup(lo[src]);
        f2 qdH = dup(hi[src]);
        const float4* w4 = (const float4*)&sWqk0[p * 32];
#pragma unroll
        for (int i = 0; i < 8; i++) {
            float4 w = w4[i];
            f2 w01 = mkf2(w.x, w.y), w23 = mkf2(w.z, w.w);
            GL[2 * i]     = ffma2(qdL, w01, GL[2 * i]);
            GL[2 * i + 1] = ffma2(qdL, w23, GL[2 * i + 1]);
            GH[2 * i]     = ffma2(qdH, w01, GH[2 * i]);
            GH[2 * i + 1] = ffma2(qdH, w23, GH[2 * i + 1]);
        }
    }

    // ---- layer 0 -> G1 ----
    f2 G1L[16], G1H[16];
    {
        float nca0 = -__ldg(ca0p), nco0 = -__ldg(co0p);
        float dwAL[2] = { __expf(nca0 * dAl[0]), __expf(nca0 * dAl[1]) };
        float dwAH[2] = { __expf(nca0 * dAh[0]), __expf(nca0 * dAh[1]) };
        float dwOL[2] = { __expf(nco0 * dOl[0]), __expf(nco0 * dOl[1]) };
        float dwOH[2] = { __expf(nco0 * dOh[0]), __expf(nco0 * dOh[1]) };
        attend2<32, 2>(GL, GH, dwAL, dwAH, dwOL, dwOH, rl, rh, sWG1, sbG1, G1L, G1H);
    }

    // ---- layer 1 -> output ----
    f2 RL[2], RH[2];
    {
        float nca1 = -__ldg(ca1p), nco1 = -__ldg(co1p);
        float dwAL[2] = { __expf(nca1 * dAl[0]), __expf(nca1 * dAl[1]) };
        float dwAH[2] = { __expf(nca1 * dAh[0]), __expf(nca1 * dAh[1]) };
        float dwOL[2] = { __expf(nco1 * dOl[0]), __expf(nco1 * dOl[1]) };
        float dwOH[2] = { __expf(nco1 * dOh[0]), __expf(nco1 * dOh[1]) };
        attend2<4, 1>(G1L, G1H, dwAL, dwAH, dwOL, dwOH, rl, rh, sWout, sbout, RL, RH);
    }

    ((float4*)out)[r0] = make_float4(f2lo(RL[0]), f2hi(RL[0]), f2lo(RL[1]), f2hi(RL[1]));
    if (r1 < n)
        ((float4*)out)[r1] = make_float4(f2lo(RH[0]), f2hi(RH[0]), f2lo(RH[1]), f2hi(RH[1]));
}

// ---------------- launch -----------------------------------------------------
extern "C" void kernel_launch(void* const* d_in, const int* in_sizes, int n_in,
                              void* d_out, int out_size)
{
    const float* obs   = (const float*)d_in[0];
    const float* wq0   = (const float*)d_in[1];
    const float* wak0  = (const float*)d_in[2];
    const float* wav0  = (const float*)d_in[3];
    const float* wok0  = (const float*)d_in[4];
    const float* wov0  = (const float*)d_in[5];
    const float* apw0  = (const float*)d_in[6];
    const float* apb0  = (const float*)d_in[7];
    const float* opw0  = (const float*)d_in[8];
    const float* opb0  = (const float*)d_in[9];
    const float* fpw0  = (const float*)d_in[10];
    const float* fpb0  = (const float*)d_in[11];
    const float* ca0   = (const float*)d_in[12];
    const float* co0   = (const float*)d_in[13];
    const float* wq1   = (const float*)d_in[14];
    const float* wak1  = (const float*)d_in[15];
    const float* wav1  = (const float*)d_in[16];
    const float* wok1  = (const float*)d_in[17];
    const float* wov1  = (const float*)d_in[18];
    const float* apw1  = (const float*)d_in[19];
    const float* apb1  = (const float*)d_in[20];
    const float* opw1  = (const float*)d_in[21];
    const float* opb1  = (const float*)d_in[22];
    const float* fpw1  = (const float*)d_in[23];
    const float* fpb1  = (const float*)d_in[24];
    const float* ca1   = (const float*)d_in[25];
    const float* co1   = (const float*)d_in[26];
    const float* headw = (const float*)d_in[27];
    const float* headb = (const float*)d_in[28];

    int n = in_sizes[0] / 37;

    pk<<<93, 512>>>(wq0, wak0, wok0, wq1, wak1, wok1,
                    wav0, apw0, wov0, opw0, wav1, apw1, wov1, opw1,
                    fpw0, fpw1, fpb0, apb0, opb0, fpb1, apb1, opb1,
                    headw, headb);

    cudaFuncSetAttribute(actor_main, cudaFuncAttributeMaxDynamicSharedMemorySize, SM_TOTAL);

    int grid = (n + MROWS - 1) / MROWS;

    cudaLaunchConfig_t cfg = {};
    cfg.gridDim  = dim3((unsigned)grid, 1, 1);
    cfg.blockDim = dim3(MT, 1, 1);
    cfg.dynamicSmemBytes = SM_TOTAL;
    cfg.stream = 0;
    cudaLaunchAttribute attrs[1];
    attrs[0].id = cudaLaunchAttributeProgrammaticStreamSerialization;
    attrs[0].val.programmaticStreamSerializationAllowed = 1;
    cfg.attrs = attrs;
    cfg.numAttrs = 1;

    cudaLaunchKernelEx(&cfg, actor_main, obs, ca0, co0, ca1, co1, (float*)d_out, n);
}

// round 13
// speedup vs baseline: 1.2897x; 1.1402x over previous
#include <cuda_runtime.h>
#include <math.h>
#include <stdint.h>

// ---------------- folded-weight scratch (device globals) -------------------
__device__ float g_Wqk0[19 * 32];
__device__ float g_WG1[36 * 32];
__device__ float g_bG1[32];
__device__ float g_Wout[36 * 4];
__device__ float g_bout[4];

#define QK_SCALE 0.17677669529663687f   // 1/sqrt(32)

// ---------------- packed f32x2 helpers --------------------------------------
struct f2 { unsigned long long v; };

__device__ __forceinline__ f2 mkf2(float lo, float hi) {
    f2 r; asm("mov.b64 %0,{%1,%2};" : "=l"(r.v) : "f"(lo), "f"(hi)); return r;
}
__device__ __forceinline__ void unf2(f2 a, float& lo, float& hi) {
    asm("mov.b64 {%0,%1},%2;" : "=f"(lo), "=f"(hi) : "l"(a.v));
}
__device__ __forceinline__ float f2lo(f2 a) { float l, h; unf2(a, l, h); return l; }
__device__ __forceinline__ float f2hi(f2 a) { float l, h; unf2(a, l, h); return h; }
__device__ __forceinline__ f2 dup(float x) { return mkf2(x, x); }
__device__ __forceinline__ f2 ffma2(f2 a, f2 b, f2 c) {
    f2 r; asm("fma.rn.f32x2 %0,%1,%2,%3;" : "=l"(r.v) : "l"(a.v), "l"(b.v), "l"(c.v)); return r;
}
__device__ __forceinline__ float sigf(float d) {   // 1/(1+exp(-d))
    float e = __expf(-d);
    float r;
    asm("rcp.approx.f32 %0,%1;" : "=f"(r) : "f"(1.f + e));
    return r;
}

// ---------------- mbarrier / bulk-copy helpers -------------------------------
__device__ __forceinline__ uint32_t smem_u32(const void* p) {
    return (uint32_t)__cvta_generic_to_shared(p);
}
#define MBAR_INIT(addr, cnt) \
    asm volatile("mbarrier.init.shared.b64 [%0], %1;" :: "r"(addr), "r"(cnt) : "memory")
#define MBAR_EXPECT_TX(addr, bytes) \
    asm volatile("mbarrier.arrive.expect_tx.shared.b64 _, [%0], %1;" :: "r"(addr), "r"(bytes) : "memory")
#define BULK_G2S(dst, src, bytes, mbar) \
    asm volatile("cp.async.bulk.shared::cta.global.mbarrier::complete_tx::bytes [%0], [%1], %2, [%3];" \
                 :: "r"(dst), "l"(src), "r"(bytes), "r"(mbar) : "memory")
#define MBAR_WAIT(addr, parity) do {                                             \
    asm volatile(                                                                \
        "{\n\t.reg .pred P1;\n\t"                                                \
        "WAIT_LOOP_%=:\n\t"                                                      \
        "mbarrier.try_wait.parity.acquire.cta.shared::cta.b64 P1, [%0], %1, 0x989680;\n\t" \
        "@P1 bra.uni WAIT_DONE_%=;\n\t"                                          \
        "bra.uni WAIT_LOOP_%=;\n\t"                                              \
        "WAIT_DONE_%=:\n\t}"                                                     \
        :: "r"(addr), "r"(parity) : "memory");                                   \
} while (0)

// ---------------- single precompute kernel (unchanged) -----------------------
__global__ void __launch_bounds__(512, 1)
pk(const float* __restrict__ wq0,  const float* __restrict__ wak0,
   const float* __restrict__ wok0,
   const float* __restrict__ wq1,  const float* __restrict__ wak1,
   const float* __restrict__ wok1,
   const float* __restrict__ wav0, const float* __restrict__ apw0,
   const float* __restrict__ wov0, const float* __restrict__ opw0,
   const float* __restrict__ wav1, const float* __restrict__ apw1,
   const float* __restrict__ wov1, const float* __restrict__ opw1,
   const float* __restrict__ fpw0, const float* __restrict__ fpw1,
   const float* __restrict__ fpb0, const float* __restrict__ apb0,
   const float* __restrict__ opb0,
   const float* __restrict__ fpb1, const float* __restrict__ apb1,
   const float* __restrict__ opb1,
   const float* __restrict__ headw, const float* __restrict__ headb)
{
    __shared__ float sh[512];
    __shared__ float svec[128], sT[128], sW[128];
    __shared__ float sX[512];
    int bid = blockIdx.x, tid = threadIdx.x;

    if (bid < 19) {
        int p = bid;
        int t = tid >> 4, ci = tid & 15, h = t & 3;
        const float* wk; int j;
        if (t < 24) { wk = wak0; j = t >> 2; } else { wk = wok0; j = (t - 24) >> 2; }
        const float4* a4 = (const float4*)(wq0 + p * 512 + h * 128 + ci * 8);
        const float4* b4 = (const float4*)(wk + j * 512 + h * 128 + ci * 8);
        float4 a0 = a4[0], a1 = a4[1], b0 = b4[0], b1 = b4[1];
        float s = a0.x * b0.x + a0.y * b0.y + a0.z * b0.z + a0.w * b0.w
                + a1.x * b1.x + a1.y * b1.y + a1.z * b1.z + a1.w * b1.w;
#pragma unroll
        for (int off = 8; off; off >>= 1) s += __shfl_xor_sync(0xffffffffu, s, off);
        if (ci == 0) g_Wqk0[p * 32 + t] = s * QK_SCALE;
    } else if (bid < 91) {
        bool isW1 = (bid < 55);
        int t = isW1 ? bid - 19 : bid - 55;
        int h = t & 3;
        const float* wv; const float* pw; int j;
        if (isW1) {
            if (t < 28) { wv = wav0; pw = apw0; j = t >> 2; }
            else        { wv = wov0; pw = opw0; j = (t - 28) >> 2; }
        } else {
            if (t < 28) { wv = wav1; pw = apw1; j = t >> 2; }
            else        { wv = wov1; pw = opw1; j = (t - 28) >> 2; }
        }
        const float* fpw = isW1 ? fpw0 : fpw1;
        int q = tid >> 7, m = tid & 127;

        float pwv[32], fv[32];
        const float* baseT = pw + h * 16384 + q * 4096 + m;
        const float* baseW = fpw + (t < 28 ? 0 : 16384) + q * 4096 + m;
#pragma unroll
        for (int i = 0; i < 32; i++) pwv[i] = __ldg(baseT + i * 128);
#pragma unroll
        for (int i = 0; i < 32; i++) fv[i] = __ldg(baseW + i * 128);
        float4 hw = make_float4(0.f, 0.f, 0.f, 0.f);
        if (!isW1 && tid < 128) hw = *(const float4*)(headw + tid * 4);
        if (tid < 128) svec[tid] = wv[j * 512 + h * 128 + tid];
        __syncthreads();

        float s = 0.f;
#pragma unroll
        for (int i = 0; i < 32; i++) s += svec[q * 32 + i] * pwv[i];
        sh[tid] = s;
        __syncthreads();
        if (tid < 128)
            sT[tid] = (sh[tid] + sh[tid + 128]) + (sh[tid + 256] + sh[tid + 384]);
        __syncthreads();

        s = 0.f;
#pragma unroll
        for (int i = 0; i < 32; i++) s += sT[q * 32 + i] * fv[i];
        sh[tid] = s;
        __syncthreads();
        if (tid < 128)
            sW[tid] = (sh[tid] + sh[tid + 128]) + (sh[tid + 256] + sh[tid + 384]);
        __syncthreads();

        if (isW1) {
            float xa[4] = {0.f, 0.f, 0.f, 0.f};
            const float* wqc = wq1 + tid;
#pragma unroll 32
            for (int mm = 0; mm < 128; mm++)
                xa[mm & 3] += sW[mm] * __ldg(wqc + mm * 512);
            sX[tid] = (xa[0] + xa[1]) + (xa[2] + xa[3]);
            __syncthreads();
            int t2 = tid >> 4, ci = tid & 15, h2 = t2 & 3;
            const float* wk; int j2;
            if (t2 < 24) { wk = wak1; j2 = t2 >> 2; } else { wk = wok1; j2 = (t2 - 24) >> 2; }
            const float4* w4 = (const float4*)(wk + j2 * 512 + h2 * 128 + ci * 8);
            float4 wa = w4[0], wb = w4[1];
            const float* xs = sX + h2 * 128 + ci * 8;
            float s2 = xs[0] * wa.x + xs[1] * wa.y + xs[2] * wa.z + xs[3] * wa.w
                     + xs[4] * wb.x + xs[5] * wb.y + xs[6] * wb.z + xs[7] * wb.w;
#pragma unroll
            for (int off = 8; off; off >>= 1) s2 += __shfl_xor_sync(0xffffffffu, s2, off);
            if (ci == 0) g_WG1[t * 32 + t2] = s2 * QK_SCALE;
        } else {
            if (tid < 128) {
                float w0 = sW[tid];
                sh[tid]       = w0 * hw.x;
                sh[tid + 128] = w0 * hw.y;
                sh[tid + 256] = w0 * hw.z;
                sh[tid + 384] = w0 * hw.w;
            }
            __syncthreads();
            int w = tid >> 5, lane = tid & 31;
            if (w < 4) {
                float s2 = sh[w * 128 + lane] + sh[w * 128 + lane + 32]
                         + sh[w * 128 + lane + 64] + sh[w * 128 + lane + 96];
#pragma unroll
                for (int off = 16; off; off >>= 1) s2 += __shfl_xor_sync(0xffffffffu, s2, off);
                if (lane == 0) g_Wout[t * 4 + w] = s2;
            }
        }
    } else if (bid == 91) {
        int q = tid >> 7, m = tid & 127;
        float fa[32], fo[32];
        const float* basea = fpw0 + q * 4096 + m;
        const float* baseo = fpw0 + 16384 + q * 4096 + m;
#pragma unroll
        for (int i = 0; i < 32; i++) fa[i] = __ldg(basea + i * 128);
#pragma unroll
        for (int i = 0; i < 32; i++) fo[i] = __ldg(baseo + i * 128);
        float s = 0.f;
#pragma unroll
        for (int i = 0; i < 32; i++) {
            int m1 = q * 32 + i;
            s += apb0[m1] * fa[i] + opb0[m1] * fo[i];
        }
        sh[tid] = s;
        __syncthreads();
        if (tid < 128)
            sW[tid] = fpb0[tid] + (sh[tid] + sh[tid + 128]) + (sh[tid + 256] + sh[tid + 384]);
        __syncthreads();
        float xa[4] = {0.f, 0.f, 0.f, 0.f};
        const float* wqc = wq1 + tid;
#pragma unroll 32
        for (int mm = 0; mm < 128; mm++)
            xa[mm & 3] += sW[mm] * __ldg(wqc + mm * 512);
        sX[tid] = (xa[0] + xa[1]) + (xa[2] + xa[3]);
        __syncthreads();
        int t2 = tid >> 4, ci = tid & 15, h2 = t2 & 3;
        const float* wk; int j2;
        if (t2 < 24) { wk = wak1; j2 = t2 >> 2; } else { wk = wok1; j2 = (t2 - 24) >> 2; }
        const float4* w4 = (const float4*)(wk + j2 * 512 + h2 * 128 + ci * 8);
        float4 wa = w4[0], wb = w4[1];
        const float* xs = sX + h2 * 128 + ci * 8;
        float s2 = xs[0] * wa.x + xs[1] * wa.y + xs[2] * wa.z + xs[3] * wa.w
                 + xs[4] * wb.x + xs[5] * wb.y + xs[6] * wb.z + xs[7] * wb.w;
#pragma unroll
        for (int off = 8; off; off >>= 1) s2 += __shfl_xor_sync(0xffffffffu, s2, off);
        if (ci == 0) g_bG1[t2] = s2 * QK_SCALE;
    } else {
        int q = tid >> 7, m = tid & 127;
        float fa[32], fo[32];
        const float* basea = fpw1 + q * 4096 + m;
        const float* baseo = fpw1 + 16384 + q * 4096 + m;
#pragma unroll
        for (int i = 0; i < 32; i++) fa[i] = __ldg(basea + i * 128);
#pragma unroll
        for (int i = 0; i < 32; i++) fo[i] = __ldg(baseo + i * 128);
        float4 hw = make_float4(0.f, 0.f, 0.f, 0.f);
        if (tid < 128) hw = *(const float4*)(headw + tid * 4);
        float s = 0.f;
#pragma unroll
        for (int i = 0; i < 32; i++) {
            int m1 = q * 32 + i;
            s += apb1[m1] * fa[i] + opb1[m1] * fo[i];
        }
        sh[tid] = s;
        __syncthreads();
        if (tid < 128)
            sW[tid] = fpb1[tid] + (sh[tid] + sh[tid + 128]) + (sh[tid + 256] + sh[tid + 384]);
        __syncthreads();
        if (tid < 128) {
            float b = sW[tid];
            sh[tid]       = b * hw.x;
            sh[tid + 128] = b * hw.y;
            sh[tid + 256] = b * hw.z;
            sh[tid + 384] = b * hw.w;
        }
        __syncthreads();
        int w = tid >> 5, lane = tid & 31;
        if (w < 4) {
            float s2 = sh[w * 128 + lane] + sh[w * 128 + lane + 32]
                     + sh[w * 128 + lane + 64] + sh[w * 128 + lane + 96];
#pragma unroll
            for (int off = 16; off; off >>= 1) s2 += __shfl_xor_sync(0xffffffffu, s2, off);
            if (lane == 0) g_bout[w] = headb[w] + s2;
        }
    }
}

// ---------------- main kernel: R10 structure + TMA bulk obs staging ----------
struct Row {
    float nbv[2][7];
    float dnbv[7];
    float obf[2][2];
    float dobf[2];
};

template <int W, int PASSES>
__device__ __forceinline__ void attend2(
    const f2 (&GL)[16], const f2 (&GH)[16],
    const float (&dwAL)[2], const float (&dwAH)[2],
    const float (&dwOL)[2], const float (&dwOH)[2],
    const Row& rl, const Row& rh,
    const float* __restrict__ wtab, const float* __restrict__ bias,
    f2* OUTL, f2* OUTH)
{
#define GET(Gr, t) (((t) & 1) ? f2hi(Gr[(t) >> 1]) : f2lo(Gr[(t) >> 1]))
    float sAL[4], sAH[4], sOL[4], sOH[4];
#pragma unroll
    for (int h = 0; h < 4; h++) {
        float d0L = 0.f, d1L = 0.f, d0H = 0.f, d1H = 0.f;
#pragma unroll
        for (int j = 0; j < 6; j++) {
            float gl = GET(GL, j * 4 + h), gh = GET(GH, j * 4 + h);
            d0L = fmaf(rl.nbv[0][j], gl, d0L);
            d1L = fmaf(rl.nbv[1][j], gl, d1L);
            d0H = fmaf(rh.nbv[0][j], gh, d0H);
            d1H = fmaf(rh.nbv[1][j], gh, d1H);
        }
        sAL[h] = sigf(d0L * dwAL[0] - d1L * dwAL[1]);
        sAH[h] = sigf(d0H * dwAH[0] - d1H * dwAH[1]);
        float g24L = GET(GL, 24 + h), g28L = GET(GL, 28 + h);
        float g24H = GET(GH, 24 + h), g28H = GET(GH, 28 + h);
        float e0L = rl.obf[0][0] * g24L + rl.obf[0][1] * g28L;
        float e1L = rl.obf[1][0] * g24L + rl.obf[1][1] * g28L;
        float e0H = rh.obf[0][0] * g24H + rh.obf[0][1] * g28H;
        float e1H = rh.obf[1][0] * g24H + rh.obf[1][1] * g28H;
        sOL[h] = sigf(e0L * dwOL[0] - e1L * dwOL[1]);
        sOH[h] = sigf(e0H * dwOH[0] - e1H * dwOH[1]);
    }
#undef GET

    constexpr int PW = W / PASSES;   // outputs per pass
    constexpr int PP = PW / 2;       // f2 pairs per pass
#pragma unroll
    for (int pass = 0; pass < PASSES; pass++) {
        f2 AL[PP], AH[PP];
#pragma unroll
        for (int i = 0; i < PP; i++) {
            f2 b = *(const f2*)&bias[pass * PW + 2 * i];
            AL[i] = b; AH[i] = b;
        }
#pragma unroll
        for (int h = 0; h < 4; h++) {
#pragma unroll
            for (int j = 0; j < 9; j++) {
                float uL, uH; int tu;
                if (j < 7) {
                    uL = fmaf(sAL[h], rl.dnbv[j], rl.nbv[1][j]);
                    uH = fmaf(sAH[h], rh.dnbv[j], rh.nbv[1][j]);
                    tu = j * 4 + h;
                } else {
                    int jo = j - 7;
                    uL = fmaf(sOL[h], rl.dobf[jo], rl.obf[1][jo]);
                    uH = fmaf(sOH[h], rh.dobf[jo], rh.obf[1][jo]);
                    tu = 28 + jo * 4 + h;
                }
                f2 uvL = dup(uL), uvH = dup(uH);
                const float4* row = (const float4*)&wtab[tu * W + pass * PW];
#pragma unroll
                for (int i = 0; i < PP / 2; i++) {
                    float4 w = row[i];               // one LDS.128 = 4 unique weights
                    f2 w01 = mkf2(w.x, w.y);
                    f2 w23 = mkf2(w.z, w.w);
                    AL[2 * i]     = ffma2(uvL, w01, AL[2 * i]);
                    AL[2 * i + 1] = ffma2(uvL, w23, AL[2 * i + 1]);
                    AH[2 * i]     = ffma2(uvH, w01, AH[2 * i]);
                    AH[2 * i + 1] = ffma2(uvH, w23, AH[2 * i + 1]);
                }
            }
        }
#pragma unroll
        for (int i = 0; i < PP; i++) {
            OUTL[pass * PP + i] = AL[i];
            OUTH[pass * PP + i] = AH[i];
        }
    }
}

// smem layout (448 rows/block, 224 threads, 2 rows/thread, 2 blocks/SM)
#define MT           224
#define MROWS        448
#define SM_OBS_F     (MROWS * 37)
#define SM_OBS_B     (SM_OBS_F * 4)                 // 66304 B (16B multiple)
#define SM_WQK0_OFF  SM_OBS_B                       // 608 floats
#define SM_WG1_OFF   (SM_WQK0_OFF + 608 * 4)        // 1152 floats
#define SM_WOUT_OFF  (SM_WG1_OFF + 1152 * 4)        // 144 floats
#define SM_BG1_OFF   (SM_WOUT_OFF + 144 * 4)        // 32 floats
#define SM_BOUT_OFF  (SM_BG1_OFF + 32 * 4)          // 4 floats
#define SM_TOTAL     (SM_BOUT_OFF + 4 * 4)          // 74064 B

__global__ void __launch_bounds__(MT, 2)
actor_main(const float* __restrict__ obs,
           const float* __restrict__ ca0p, const float* __restrict__ co0p,
           const float* __restrict__ ca1p, const float* __restrict__ co1p,
           float* __restrict__ out, int n)
{
    extern __shared__ __align__(16) unsigned char smbuf[];
    float* sObs  = (float*)smbuf;
    float* sWqk0 = (float*)(smbuf + SM_WQK0_OFF);
    float* sWG1  = (float*)(smbuf + SM_WG1_OFF);
    float* sWout = (float*)(smbuf + SM_WOUT_OFF);
    float* sbG1  = (float*)(smbuf + SM_BG1_OFF);
    float* sbout = (float*)(smbuf + SM_BOUT_OFF);
    __shared__ __align__(8) unsigned long long mbar_storage;

    int tid = threadIdx.x;
    uint32_t mbar = smem_u32(&mbar_storage);

    // ---- async bulk-copy obs tile (independent of pk; overlaps PDL wait) ----
    {
        long total_bytes = (long)n * 37 * 4;
        long off = (long)blockIdx.x * SM_OBS_B;
        long rem = total_bytes - off;
        unsigned bytes = (rem >= SM_OBS_B) ? (unsigned)SM_OBS_B : (unsigned)rem;
        if (tid == 0) {
            MBAR_INIT(mbar, 1);
            // fence init before copy uses it (same thread: program order OK for
            // mbarrier ops issued by the same thread via async proxy ordering)
            asm volatile("fence.proxy.async.shared::cta;" ::: "memory");
            if ((bytes & 15u) == 0u && bytes > 0u) {
                MBAR_EXPECT_TX(mbar, bytes);
                BULK_G2S(smem_u32(sObs), (const char*)obs + off, bytes, mbar);
            } else {
                // fallback (never taken for the bench shapes): copy via loop
                for (unsigned i = 0; i < bytes / 4; i++)
                    sObs[i] = *((const float*)((const char*)obs + off) + i);
                MBAR_EXPECT_TX(mbar, 0);
            }
        }
    }

    // ---- wait for pk's global writes, then stage folded weights ----
    cudaGridDependencySynchronize();

    for (int i = tid; i < 608;  i += MT) sWqk0[i] = g_Wqk0[i];
    for (int i = tid; i < 1152; i += MT) sWG1[i]  = g_WG1[i];
    if (tid < 144) sWout[tid] = g_Wout[tid];
    if (tid < 32) sbG1[tid] = g_bG1[tid];
    if (tid < 4)  sbout[tid] = g_bout[tid];
    __syncthreads();                 // weights visible + mbar init visible
    MBAR_WAIT(mbar, 0);              // obs tile delivered

    int r0 = blockIdx.x * MROWS + tid;
    if (r0 >= n) return;
    int r1 = r0 + MT;
    const float* lo = &sObs[tid * 37];
    const float* hi = &sObs[(tid + MT) * 37];

    // ---- scalar per-row features ----
    Row rl, rh;
#pragma unroll
    for (int k = 0; k < 2; k++) {
#pragma unroll
        for (int j = 0; j < 6; j++) {
            rl.nbv[k][j] = lo[12 + 6 * k + j];
            rh.nbv[k][j] = hi[12 + 6 * k + j];
        }
        rl.nbv[k][6] = lo[24 + k];
        rh.nbv[k][6] = hi[24 + k];
        rl.obf[k][0] = lo[26 + 2 * k]; rl.obf[k][1] = lo[27 + 2 * k];
        rh.obf[k][0] = hi[26 + 2 * k]; rh.obf[k][1] = hi[27 + 2 * k];
    }
#pragma unroll
    for (int j = 0; j < 7; j++) {
        rl.dnbv[j] = rl.nbv[0][j] - rl.nbv[1][j];
        rh.dnbv[j] = rh.nbv[0][j] - rh.nbv[1][j];
    }
#pragma unroll
    for (int j = 0; j < 2; j++) {
        rl.dobf[j] = rl.obf[0][j] - rl.obf[1][j];
        rh.dobf[j] = rh.obf[0][j] - rh.obf[1][j];
    }

    // ---- distances (shared by both layers) ----
    float dAl[2], dAh[2], dOl[2], dOh[2];
    {
        float axl = lo[0], ayl = lo[1], axh = hi[0], ayh = hi[1];
#pragma unroll
        for (int k = 0; k < 2; k++) {
            float dx = axl - rl.nbv[k][0], dy = ayl - rl.nbv[k][1];
            dAl[k] = sqrtf(dx * dx + dy * dy);
            dx = axh - rh.nbv[k][0]; dy = ayh - rh.nbv[k][1];
            dAh[k] = sqrtf(dx * dx + dy * dy);
            dx = axl - rl.obf[k][0]; dy = ayl - rl.obf[k][1];
            dOl[k] = sqrtf(dx * dx + dy * dy);
            dx = axh - rh.obf[k][0]; dy = ayh - rh.obf[k][1];
            dOh[k] = sqrtf(dx * dx + dy * dy);
        }
    }

    // ---- layer-0 logit features: G = qf @ Wqk0 (output-pair layout) ----
    f2 GL[16], GH[16];
#pragma unroll
    for (int t = 0; t < 16; t++) { GL[t] = f2{0ull}; GH[t] = f2{0ull}; }
#pragma unroll
    for (int p = 0; p < 19; p++) {
        int src = (p < 12) ? p : p + 18;
        f2 qdL = dup(lo[src]);
        f2 qdH = dup(hi[src]);
        const float4* w4 = (const float4*)&sWqk0[p * 32];
#pragma unroll
        for (int i = 0; i < 8; i++) {
            float4 w = w4[i];
            f2 w01 = mkf2(w.x, w.y), w23 = mkf2(w.z, w.w);
            GL[2 * i]     = ffma2(qdL, w01, GL[2 * i]);
            GL[2 * i + 1] = ffma2(qdL, w23, GL[2 * i + 1]);
            GH[2 * i]     = ffma2(qdH, w01, GH[2 * i]);
            GH[2 * i + 1] = ffma2(qdH, w23, GH[2 * i + 1]);
        }
    }

    // ---- layer 0 -> G1 ----
    f2 G1L[16], G1H[16];
    {
        float nca0 = -__ldg(ca0p), nco0 = -__ldg(co0p);
        float dwAL[2] = { __expf(nca0 * dAl[0]), __expf(nca0 * dAl[1]) };
        float dwAH[2] = { __expf(nca0 * dAh[0]), __expf(nca0 * dAh[1]) };
        float dwOL[2] = { __expf(nco0 * dOl[0]), __expf(nco0 * dOl[1]) };
        float dwOH[2] = { __expf(nco0 * dOh[0]), __expf(nco0 * dOh[1]) };
        attend2<32, 2>(GL, GH, dwAL, dwAH, dwOL, dwOH, rl, rh, sWG1, sbG1, G1L, G1H);
    }

    // ---- layer 1 -> output ----
    f2 RL[2], RH[2];
    {
        float nca1 = -__ldg(ca1p), nco1 = -__ldg(co1p);
        float dwAL[2] = { __expf(nca1 * dAl[0]), __expf(nca1 * dAl[1]) };
        float dwAH[2] = { __expf(nca1 * dAh[0]), __expf(nca1 * dAh[1]) };
        float dwOL[2] = { __expf(nco1 * dOl[0]), __expf(nco1 * dOl[1]) };
        float dwOH[2] = { __expf(nco1 * dOh[0]), __expf(nco1 * dOh[1]) };
        attend2<4, 1>(G1L, G1H, dwAL, dwAH, dwOL, dwOH, rl, rh, sWout, sbout, RL, RH);
    }

    ((float4*)out)[r0] = make_float4(f2lo(RL[0]), f2hi(RL[0]), f2lo(RL[1]), f2hi(RL[1]));
    if (r1 < n)
        ((float4*)out)[r1] = make_float4(f2lo(RH[0]), f2hi(RH[0]), f2lo(RH[1]), f2hi(RH[1]));
}

// ---------------- launch -----------------------------------------------------
extern "C" void kernel_launch(void* const* d_in, const int* in_sizes, int n_in,
                              void* d_out, int out_size)
{
    const float* obs   = (const float*)d_in[0];
    const float* wq0   = (const float*)d_in[1];
    const float* wak0  = (const float*)d_in[2];
    const float* wav0  = (const float*)d_in[3];
    const float* wok0  = (const float*)d_in[4];
    const float* wov0  = (const float*)d_in[5];
    const float* apw0  = (const float*)d_in[6];
    const float* apb0  = (const float*)d_in[7];
    const float* opw0  = (const float*)d_in[8];
    const float* opb0  = (const float*)d_in[9];
    const float* fpw0  = (const float*)d_in[10];
    const float* fpb0  = (const float*)d_in[11];
    const float* ca0   = (const float*)d_in[12];
    const float* co0   = (const float*)d_in[13];
    const float* wq1   = (const float*)d_in[14];
    const float* wak1  = (const float*)d_in[15];
    const float* wav1  = (const float*)d_in[16];
    const float* wok1  = (const float*)d_in[17];
    const float* wov1  = (const float*)d_in[18];
    const float* apw1  = (const float*)d_in[19];
    const float* apb1  = (const float*)d_in[20];
    const float* opw1  = (const float*)d_in[21];
    const float* opb1  = (const float*)d_in[22];
    const float* fpw1  = (const float*)d_in[23];
    const float* fpb1  = (const float*)d_in[24];
    const float* ca1   = (const float*)d_in[25];
    const float* co1   = (const float*)d_in[26];
    const float* headw = (const float*)d_in[27];
    const float* headb = (const float*)d_in[28];

    int n = in_sizes[0] / 37;

    pk<<<93, 512>>>(wq0, wak0, wok0, wq1, wak1, wok1,
                    wav0, apw0, wov0, opw0, wav1, apw1, wov1, opw1,
                    fpw0, fpw1, fpb0, apb0, opb0, fpb1, apb1, opb1,
                    headw, headb);

    cudaFuncSetAttribute(actor_main, cudaFuncAttributeMaxDynamicSharedMemorySize, SM_TOTAL);

    int grid = (n + MROWS - 1) / MROWS;

    cudaLaunchConfig_t cfg = {};
    cfg.gridDim  = dim3((unsigned)grid, 1, 1);
    cfg.blockDim = dim3(MT, 1, 1);
    cfg.dynamicSmemBytes = SM_TOTAL;
    cfg.stream = 0;
    cudaLaunchAttribute attrs[1];
    attrs[0].id = cudaLaunchAttributeProgrammaticStreamSerialization;
    attrs[0].val.programmaticStreamSerializationAllowed = 1;
    cfg.attrs = attrs;
    cfg.numAttrs = 1;

    cudaLaunchKernelEx(&cfg, actor_main, obs, ca0, co0, ca1, co1, (float*)d_out, n);
}

// round 14
// speedup vs baseline: 1.4100x; 1.0932x over previous
#include <cuda_runtime.h>
#include <math.h>
#include <stdint.h>

// ---------------- fused folded-weight table (device global) ----------------
// layout: [Wqk0 608 | WG1 1152 | Wout 144 | bG1 32 | bout 4] = 1940 floats
#define WT_WQK0  0
#define WT_WG1   608
#define WT_WOUT  1760
#define WT_BG1   1904
#define WT_BOUT  1936
#define WT_FLOATS 1940
#define WT_BYTES (WT_FLOATS * 4)     // 7760, multiple of 16
__device__ __align__(16) float g_wtab[WT_FLOATS];

#define QK_SCALE 0.17677669529663687f   // 1/sqrt(32)

// ---------------- packed f32x2 helpers --------------------------------------
struct f2 { unsigned long long v; };

__device__ __forceinline__ f2 mkf2(float lo, float hi) {
    f2 r; asm("mov.b64 %0,{%1,%2};" : "=l"(r.v) : "f"(lo), "f"(hi)); return r;
}
__device__ __forceinline__ void unf2(f2 a, float& lo, float& hi) {
    asm("mov.b64 {%0,%1},%2;" : "=f"(lo), "=f"(hi) : "l"(a.v));
}
__device__ __forceinline__ float f2lo(f2 a) { float l, h; unf2(a, l, h); return l; }
__device__ __forceinline__ float f2hi(f2 a) { float l, h; unf2(a, l, h); return h; }
__device__ __forceinline__ f2 dup(float x) { return mkf2(x, x); }
__device__ __forceinline__ f2 ffma2(f2 a, f2 b, f2 c) {
    f2 r; asm("fma.rn.f32x2 %0,%1,%2,%3;" : "=l"(r.v) : "l"(a.v), "l"(b.v), "l"(c.v)); return r;
}
__device__ __forceinline__ float sigf(float d) {   // 1/(1+exp(-d))
    float e = __expf(-d);
    float r;
    asm("rcp.approx.f32 %0,%1;" : "=f"(r) : "f"(1.f + e));
    return r;
}

// ---------------- mbarrier / bulk-copy helpers -------------------------------
__device__ __forceinline__ uint32_t smem_u32(const void* p) {
    return (uint32_t)__cvta_generic_to_shared(p);
}
#define MBAR_INIT(addr, cnt) \
    asm volatile("mbarrier.init.shared.b64 [%0], %1;" :: "r"(addr), "r"(cnt) : "memory")
#define MBAR_EXPECT_TX(addr, bytes) \
    asm volatile("mbarrier.arrive.expect_tx.shared.b64 _, [%0], %1;" :: "r"(addr), "r"(bytes) : "memory")
#define BULK_G2S(dst, src, bytes, mbar) \
    asm volatile("cp.async.bulk.shared::cta.global.mbarrier::complete_tx::bytes [%0], [%1], %2, [%3];" \
                 :: "r"(dst), "l"(src), "r"(bytes), "r"(mbar) : "memory")
#define MBAR_WAIT(addr, parity) do {                                             \
    asm volatile(                                                                \
        "{\n\t.reg .pred P1;\n\t"                                                \
        "WAIT_LOOP_%=:\n\t"                                                      \
        "mbarrier.try_wait.parity.acquire.cta.shared::cta.b64 P1, [%0], %1, 0x989680;\n\t" \
        "@P1 bra.uni WAIT_DONE_%=;\n\t"                                          \
        "bra.uni WAIT_LOOP_%=;\n\t"                                              \
        "WAIT_DONE_%=:\n\t}"                                                     \
        :: "r"(addr), "r"(parity) : "memory");                                   \
} while (0)

// ---------------- single precompute kernel -----------------------------------
__global__ void __launch_bounds__(512, 1)
pk(const float* __restrict__ wq0,  const float* __restrict__ wak0,
   const float* __restrict__ wok0,
   const float* __restrict__ wq1,  const float* __restrict__ wak1,
   const float* __restrict__ wok1,
   const float* __restrict__ wav0, const float* __restrict__ apw0,
   const float* __restrict__ wov0, const float* __restrict__ opw0,
   const float* __restrict__ wav1, const float* __restrict__ apw1,
   const float* __restrict__ wov1, const float* __restrict__ opw1,
   const float* __restrict__ fpw0, const float* __restrict__ fpw1,
   const float* __restrict__ fpb0, const float* __restrict__ apb0,
   const float* __restrict__ opb0,
   const float* __restrict__ fpb1, const float* __restrict__ apb1,
   const float* __restrict__ opb1,
   const float* __restrict__ headw, const float* __restrict__ headb)
{
    __shared__ float sh[512];
    __shared__ float svec[128], sT[128], sW[128];
    __shared__ float sX[512];
    int bid = blockIdx.x, tid = threadIdx.x;

    if (bid < 19) {
        int p = bid;
        int t = tid >> 4, ci = tid & 15, h = t & 3;
        const float* wk; int j;
        if (t < 24) { wk = wak0; j = t >> 2; } else { wk = wok0; j = (t - 24) >> 2; }
        const float4* a4 = (const float4*)(wq0 + p * 512 + h * 128 + ci * 8);
        const float4* b4 = (const float4*)(wk + j * 512 + h * 128 + ci * 8);
        float4 a0 = a4[0], a1 = a4[1], b0 = b4[0], b1 = b4[1];
        float s = a0.x * b0.x + a0.y * b0.y + a0.z * b0.z + a0.w * b0.w
                + a1.x * b1.x + a1.y * b1.y + a1.z * b1.z + a1.w * b1.w;
#pragma unroll
        for (int off = 8; off; off >>= 1) s += __shfl_xor_sync(0xffffffffu, s, off);
        if (ci == 0) g_wtab[WT_WQK0 + p * 32 + t] = s * QK_SCALE;
    } else if (bid < 91) {
        bool isW1 = (bid < 55);
        int t = isW1 ? bid - 19 : bid - 55;
        int h = t & 3;
        const float* wv; const float* pw; int j;
        if (isW1) {
            if (t < 28) { wv = wav0; pw = apw0; j = t >> 2; }
            else        { wv = wov0; pw = opw0; j = (t - 28) >> 2; }
        } else {
            if (t < 28) { wv = wav1; pw = apw1; j = t >> 2; }
            else        { wv = wov1; pw = opw1; j = (t - 28) >> 2; }
        }
        const float* fpw = isW1 ? fpw0 : fpw1;
        int q = tid >> 7, m = tid & 127;

        float pwv[32], fv[32];
        const float* baseT = pw + h * 16384 + q * 4096 + m;
        const float* baseW = fpw + (t < 28 ? 0 : 16384) + q * 4096 + m;
#pragma unroll
        for (int i = 0; i < 32; i++) pwv[i] = __ldg(baseT + i * 128);
#pragma unroll
        for (int i = 0; i < 32; i++) fv[i] = __ldg(baseW + i * 128);
        float4 hw = make_float4(0.f, 0.f, 0.f, 0.f);
        if (!isW1 && tid < 128) hw = *(const float4*)(headw + tid * 4);
        if (tid < 128) svec[tid] = wv[j * 512 + h * 128 + tid];
        __syncthreads();

        float s = 0.f;
#pragma unroll
        for (int i = 0; i < 32; i++) s += svec[q * 32 + i] * pwv[i];
        sh[tid] = s;
        __syncthreads();
        if (tid < 128)
            sT[tid] = (sh[tid] + sh[tid + 128]) + (sh[tid + 256] + sh[tid + 384]);
        __syncthreads();

        s = 0.f;
#pragma unroll
        for (int i = 0; i < 32; i++) s += sT[q * 32 + i] * fv[i];
        sh[tid] = s;
        __syncthreads();
        if (tid < 128)
            sW[tid] = (sh[tid] + sh[tid + 128]) + (sh[tid + 256] + sh[tid + 384]);
        __syncthreads();

        if (isW1) {
            float xa[4] = {0.f, 0.f, 0.f, 0.f};
            const float* wqc = wq1 + tid;
#pragma unroll 32
            for (int mm = 0; mm < 128; mm++)
                xa[mm & 3] += sW[mm] * __ldg(wqc + mm * 512);
            sX[tid] = (xa[0] + xa[1]) + (xa[2] + xa[3]);
            __syncthreads();
            int t2 = tid >> 4, ci = tid & 15, h2 = t2 & 3;
            const float* wk; int j2;
            if (t2 < 24) { wk = wak1; j2 = t2 >> 2; } else { wk = wok1; j2 = (t2 - 24) >> 2; }
            const float4* w4 = (const float4*)(wk + j2 * 512 + h2 * 128 + ci * 8);
            float4 wa = w4[0], wb = w4[1];
            const float* xs = sX + h2 * 128 + ci * 8;
            float s2 = xs[0] * wa.x + xs[1] * wa.y + xs[2] * wa.z + xs[3] * wa.w
                     + xs[4] * wb.x + xs[5] * wb.y + xs[6] * wb.z + xs[7] * wb.w;
#pragma unroll
            for (int off = 8; off; off >>= 1) s2 += __shfl_xor_sync(0xffffffffu, s2, off);
            if (ci == 0) g_wtab[WT_WG1 + t * 32 + t2] = s2 * QK_SCALE;
        } else {
            if (tid < 128) {
                float w0 = sW[tid];
                sh[tid]       = w0 * hw.x;
                sh[tid + 128] = w0 * hw.y;
                sh[tid + 256] = w0 * hw.z;
                sh[tid + 384] = w0 * hw.w;
            }
            __syncthreads();
            int w = tid >> 5, lane = tid & 31;
            if (w < 4) {
                float s2 = sh[w * 128 + lane] + sh[w * 128 + lane + 32]
                         + sh[w * 128 + lane + 64] + sh[w * 128 + lane + 96];
#pragma unroll
                for (int off = 16; off; off >>= 1) s2 += __shfl_xor_sync(0xffffffffu, s2, off);
                if (lane == 0) g_wtab[WT_WOUT + t * 4 + w] = s2;
            }
        }
    } else if (bid == 91) {
        int q = tid >> 7, m = tid & 127;
        float fa[32], fo[32];
        const float* basea = fpw0 + q * 4096 + m;
        const float* baseo = fpw0 + 16384 + q * 4096 + m;
#pragma unroll
        for (int i = 0; i < 32; i++) fa[i] = __ldg(basea + i * 128);
#pragma unroll
        for (int i = 0; i < 32; i++) fo[i] = __ldg(baseo + i * 128);
        float s = 0.f;
#pragma unroll
        for (int i = 0; i < 32; i++) {
            int m1 = q * 32 + i;
            s += apb0[m1] * fa[i] + opb0[m1] * fo[i];
        }
        sh[tid] = s;
        __syncthreads();
        if (tid < 128)
            sW[tid] = fpb0[tid] + (sh[tid] + sh[tid + 128]) + (sh[tid + 256] + sh[tid + 384]);
        __syncthreads();
        float xa[4] = {0.f, 0.f, 0.f, 0.f};
        const float* wqc = wq1 + tid;
#pragma unroll 32
        for (int mm = 0; mm < 128; mm++)
            xa[mm & 3] += sW[mm] * __ldg(wqc + mm * 512);
        sX[tid] = (xa[0] + xa[1]) + (xa[2] + xa[3]);
        __syncthreads();
        int t2 = tid >> 4, ci = tid & 15, h2 = t2 & 3;
        const float* wk; int j2;
        if (t2 < 24) { wk = wak1; j2 = t2 >> 2; } else { wk = wok1; j2 = (t2 - 24) >> 2; }
        const float4* w4 = (const float4*)(wk + j2 * 512 + h2 * 128 + ci * 8);
        float4 wa = w4[0], wb = w4[1];
        const float* xs = sX + h2 * 128 + ci * 8;
        float s2 = xs[0] * wa.x + xs[1] * wa.y + xs[2] * wa.z + xs[3] * wa.w
                 + xs[4] * wb.x + xs[5] * wb.y + xs[6] * wb.z + xs[7] * wb.w;
#pragma unroll
        for (int off = 8; off; off >>= 1) s2 += __shfl_xor_sync(0xffffffffu, s2, off);
        if (ci == 0) g_wtab[WT_BG1 + t2] = s2 * QK_SCALE;
    } else {
        int q = tid >> 7, m = tid & 127;
        float fa[32], fo[32];
        const float* basea = fpw1 + q * 4096 + m;
        const float* baseo = fpw1 + 16384 + q * 4096 + m;
#pragma unroll
        for (int i = 0; i < 32; i++) fa[i] = __ldg(basea + i * 128);
#pragma unroll
        for (int i = 0; i < 32; i++) fo[i] = __ldg(baseo + i * 128);
        float4 hw = make_float4(0.f, 0.f, 0.f, 0.f);
        if (tid < 128) hw = *(const float4*)(headw + tid * 4);
        float s = 0.f;
#pragma unroll
        for (int i = 0; i < 32; i++) {
            int m1 = q * 32 + i;
            s += apb1[m1] * fa[i] + opb1[m1] * fo[i];
        }
        sh[tid] = s;
        __syncthreads();
        if (tid < 128)
            sW[tid] = fpb1[tid] + (sh[tid] + sh[tid + 128]) + (sh[tid + 256] + sh[tid + 384]);
        __syncthreads();
        if (tid < 128) {
            float b = sW[tid];
            sh[tid]       = b * hw.x;
            sh[tid + 128] = b * hw.y;
            sh[tid + 256] = b * hw.z;
            sh[tid + 384] = b * hw.w;
        }
        __syncthreads();
        int w = tid >> 5, lane = tid & 31;
        if (w < 4) {
            float s2 = sh[w * 128 + lane] + sh[w * 128 + lane + 32]
                     + sh[w * 128 + lane + 64] + sh[w * 128 + lane + 96];
#pragma unroll
            for (int off = 16; off; off >>= 1) s2 += __shfl_xor_sync(0xffffffffu, s2, off);
            if (lane == 0) g_wtab[WT_BOUT + w] = headb[w] + s2;
        }
    }
}

// ---------------- main kernel ------------------------------------------------
struct Row {
    float nbv[2][7];
    float dnbv[7];
    float obf[2][2];
    float dobf[2];
};

template <int W, int PASSES>
__device__ __forceinline__ void attend2(
    const f2 (&GL)[16], const f2 (&GH)[16],
    const float (&dwAL)[2], const float (&dwAH)[2],
    const float (&dwOL)[2], const float (&dwOH)[2],
    const Row& rl, const Row& rh,
    const float* __restrict__ wtab, const float* __restrict__ bias,
    f2* OUTL, f2* OUTH)
{
#define GET(Gr, t) (((t) & 1) ? f2hi(Gr[(t) >> 1]) : f2lo(Gr[(t) >> 1]))
    float sAL[4], sAH[4], sOL[4], sOH[4];
#pragma unroll
    for (int h = 0; h < 4; h++) {
        float d0L = 0.f, d1L = 0.f, d0H = 0.f, d1H = 0.f;
#pragma unroll
        for (int j = 0; j < 6; j++) {
            float gl = GET(GL, j * 4 + h), gh = GET(GH, j * 4 + h);
            d0L = fmaf(rl.nbv[0][j], gl, d0L);
            d1L = fmaf(rl.nbv[1][j], gl, d1L);
            d0H = fmaf(rh.nbv[0][j], gh, d0H);
            d1H = fmaf(rh.nbv[1][j], gh, d1H);
        }
        sAL[h] = sigf(d0L * dwAL[0] - d1L * dwAL[1]);
        sAH[h] = sigf(d0H * dwAH[0] - d1H * dwAH[1]);
        float g24L = GET(GL, 24 + h), g28L = GET(GL, 28 + h);
        float g24H = GET(GH, 24 + h), g28H = GET(GH, 28 + h);
        float e0L = rl.obf[0][0] * g24L + rl.obf[0][1] * g28L;
        float e1L = rl.obf[1][0] * g24L + rl.obf[1][1] * g28L;
        float e0H = rh.obf[0][0] * g24H + rh.obf[0][1] * g28H;
        float e1H = rh.obf[1][0] * g24H + rh.obf[1][1] * g28H;
        sOL[h] = sigf(e0L * dwOL[0] - e1L * dwOL[1]);
        sOH[h] = sigf(e0H * dwOH[0] - e1H * dwOH[1]);
    }
#undef GET

    constexpr int PW = W / PASSES;
    constexpr int PP = PW / 2;
#pragma unroll
    for (int pass = 0; pass < PASSES; pass++) {
        f2 AL[PP], AH[PP];
#pragma unroll
        for (int i = 0; i < PP; i++) {
            f2 b = *(const f2*)&bias[pass * PW + 2 * i];
            AL[i] = b; AH[i] = b;
        }
#pragma unroll
        for (int h = 0; h < 4; h++) {
#pragma unroll
            for (int j = 0; j < 9; j++) {
                float uL, uH; int tu;
                if (j < 7) {
                    uL = fmaf(sAL[h], rl.dnbv[j], rl.nbv[1][j]);
                    uH = fmaf(sAH[h], rh.dnbv[j], rh.nbv[1][j]);
                    tu = j * 4 + h;
                } else {
                    int jo = j - 7;
                    uL = fmaf(sOL[h], rl.dobf[jo], rl.obf[1][jo]);
                    uH = fmaf(sOH[h], rh.dobf[jo], rh.obf[1][jo]);
                    tu = 28 + jo * 4 + h;
                }
                f2 uvL = dup(uL), uvH = dup(uH);
                const float4* row = (const float4*)&wtab[tu * W + pass * PW];
#pragma unroll
                for (int i = 0; i < PP / 2; i++) {
                    float4 w = row[i];
                    f2 w01 = mkf2(w.x, w.y);
                    f2 w23 = mkf2(w.z, w.w);
                    AL[2 * i]     = ffma2(uvL, w01, AL[2 * i]);
                    AL[2 * i + 1] = ffma2(uvL, w23, AL[2 * i + 1]);
                    AH[2 * i]     = ffma2(uvH, w01, AH[2 * i]);
                    AH[2 * i + 1] = ffma2(uvH, w23, AH[2 * i + 1]);
                }
            }
        }
#pragma unroll
        for (int i = 0; i < PP; i++) {
            OUTL[pass * PP + i] = AL[i];
            OUTH[pass * PP + i] = AH[i];
        }
    }
}

// smem layout (448 rows/block, 224 threads, 2 rows/thread, 2 blocks/SM)
#define MT           224
#define MROWS        448
#define SM_OBS_F     (MROWS * 37)
#define SM_OBS_B     (SM_OBS_F * 4)                 // 66304 B (16B multiple)
#define SM_WTAB_OFF  SM_OBS_B
#define SM_TOTAL     (SM_WTAB_OFF + WT_BYTES)       // 74064 B

__global__ void __launch_bounds__(MT, 2)
actor_main(const float* __restrict__ obs,
           const float* __restrict__ ca0p, const float* __restrict__ co0p,
           const float* __restrict__ ca1p, const float* __restrict__ co1p,
           float* __restrict__ out, int n)
{
    extern __shared__ __align__(16) unsigned char smbuf[];
    float* sObs  = (float*)smbuf;
    float* sWtab = (float*)(smbuf + SM_WTAB_OFF);
    float* sWqk0 = sWtab + WT_WQK0;
    float* sWG1  = sWtab + WT_WG1;
    float* sWout = sWtab + WT_WOUT;
    float* sbG1  = sWtab + WT_BG1;
    float* sbout = sWtab + WT_BOUT;
    __shared__ __align__(8) unsigned long long mbar_storage[2];

    int tid = threadIdx.x;
    uint32_t mbar0 = smem_u32(&mbar_storage[0]);
    uint32_t mbar1 = smem_u32(&mbar_storage[1]);

    // ---- async bulk-copy obs tile (independent of pk; overlaps PDL wait) ----
    {
        long total_bytes = (long)n * 37 * 4;
        long off = (long)blockIdx.x * SM_OBS_B;
        long rem = total_bytes - off;
        unsigned bytes = (rem >= SM_OBS_B) ? (unsigned)SM_OBS_B : (unsigned)rem;
        if (tid == 0) {
            MBAR_INIT(mbar0, 1);
            MBAR_INIT(mbar1, 1);
            asm volatile("fence.proxy.async.shared::cta;" ::: "memory");
            if ((bytes & 15u) == 0u && bytes > 0u) {
                MBAR_EXPECT_TX(mbar0, bytes);
                BULK_G2S(smem_u32(sObs), (const char*)obs + off, bytes, mbar0);
            } else {
                for (unsigned i = 0; i < bytes / 4; i++)
                    sObs[i] = *((const float*)((const char*)obs + off) + i);
                MBAR_EXPECT_TX(mbar0, 0);
            }
        }
    }
    __syncthreads();                 // mbar inits visible to all threads
    MBAR_WAIT(mbar0, 0);             // obs tile delivered (pk-independent)

    int r0 = blockIdx.x * MROWS + tid;
    bool live = (r0 < n);
    int r1 = r0 + MT;
    const float* lo = &sObs[tid * 37];
    const float* hi = &sObs[(tid + MT) * 37];

    // ---- obs-only work: features, distances, decay weights (in pk's shadow) --
    Row rl, rh;
    float dwAL0[2], dwAH0[2], dwOL0[2], dwOH0[2];
    float dwAL1[2], dwAH1[2], dwOL1[2], dwOH1[2];
    if (live) {
#pragma unroll
        for (int k = 0; k < 2; k++) {
#pragma unroll
            for (int j = 0; j < 6; j++) {
                rl.nbv[k][j] = lo[12 + 6 * k + j];
                rh.nbv[k][j] = hi[12 + 6 * k + j];
            }
            rl.nbv[k][6] = lo[24 + k];
            rh.nbv[k][6] = hi[24 + k];
            rl.obf[k][0] = lo[26 + 2 * k]; rl.obf[k][1] = lo[27 + 2 * k];
            rh.obf[k][0] = hi[26 + 2 * k]; rh.obf[k][1] = hi[27 + 2 * k];
        }
#pragma unroll
        for (int j = 0; j < 7; j++) {
            rl.dnbv[j] = rl.nbv[0][j] - rl.nbv[1][j];
            rh.dnbv[j] = rh.nbv[0][j] - rh.nbv[1][j];
        }
#pragma unroll
        for (int j = 0; j < 2; j++) {
            rl.dobf[j] = rl.obf[0][j] - rl.obf[1][j];
            rh.dobf[j] = rh.obf[0][j] - rh.obf[1][j];
        }
        float dAl[2], dAh[2], dOl[2], dOh[2];
        {
            float axl = lo[0], ayl = lo[1], axh = hi[0], ayh = hi[1];
#pragma unroll
            for (int k = 0; k < 2; k++) {
                float dx = axl - rl.nbv[k][0], dy = ayl - rl.nbv[k][1];
                dAl[k] = sqrtf(dx * dx + dy * dy);
                dx = axh - rh.nbv[k][0]; dy = ayh - rh.nbv[k][1];
                dAh[k] = sqrtf(dx * dx + dy * dy);
                dx = axl - rl.obf[k][0]; dy = ayl - rl.obf[k][1];
                dOl[k] = sqrtf(dx * dx + dy * dy);
                dx = axh - rh.obf[k][0]; dy = ayh - rh.obf[k][1];
                dOh[k] = sqrtf(dx * dx + dy * dy);
            }
        }
        float nca0 = -__ldg(ca0p), nco0 = -__ldg(co0p);
        float nca1 = -__ldg(ca1p), nco1 = -__ldg(co1p);
#pragma unroll
        for (int k = 0; k < 2; k++) {
            dwAL0[k] = __expf(nca0 * dAl[k]); dwAH0[k] = __expf(nca0 * dAh[k]);
            dwOL0[k] = __expf(nco0 * dOl[k]); dwOH0[k] = __expf(nco0 * dOh[k]);
            dwAL1[k] = __expf(nca1 * dAl[k]); dwAH1[k] = __expf(nca1 * dAh[k]);
            dwOL1[k] = __expf(nco1 * dOl[k]); dwOH1[k] = __expf(nco1 * dOh[k]);
        }
    }

    // ---- wait for pk, then bulk-copy the fused weight table -----------------
    cudaGridDependencySynchronize();
    if (tid == 0) {
        MBAR_EXPECT_TX(mbar1, WT_BYTES);
        BULK_G2S(smem_u32(sWtab), (const char*)g_wtab, WT_BYTES, mbar1);
    }
    MBAR_WAIT(mbar1, 0);             // weights delivered (init synced earlier)

    if (!live) return;

    // ---- layer-0 logit features: G = qf @ Wqk0 (output-pair layout) ----
    f2 GL[16], GH[16];
#pragma unroll
    for (int t = 0; t < 16; t++) { GL[t] = f2{0ull}; GH[t] = f2{0ull}; }
#pragma unroll
    for (int p = 0; p < 19; p++) {
        int src = (p < 12) ? p : p + 18;
        f2 qdL = dup(lo[src]);
        f2 qdH = dup(hi[src]);
        const float4* w4 = (const float4*)&sWqk0[p * 32];
#pragma unroll
        for (int i = 0; i < 8; i++) {
            float4 w = w4[i];
            f2 w01 = mkf2(w.x, w.y), w23 = mkf2(w.z, w.w);
            GL[2 * i]     = ffma2(qdL, w01, GL[2 * i]);
            GL[2 * i + 1] = ffma2(qdL, w23, GL[2 * i + 1]);
            GH[2 * i]     = ffma2(qdH, w01, GH[2 * i]);
            GH[2 * i + 1] = ffma2(qdH, w23, GH[2 * i + 1]);
        }
    }

    // ---- layer 0 -> G1 ----
    f2 G1L[16], G1H[16];
    attend2<32, 2>(GL, GH, dwAL0, dwAH0, dwOL0, dwOH0, rl, rh, sWG1, sbG1, G1L, G1H);

    // ---- layer 1 -> output ----
    f2 RL[2], RH[2];
    attend2<4, 1>(G1L, G1H, dwAL1, dwAH1, dwOL1, dwOH1, rl, rh, sWout, sbout, RL, RH);

    ((float4*)out)[r0] = make_float4(f2lo(RL[0]), f2hi(RL[0]), f2lo(RL[1]), f2hi(RL[1]));
    if (r1 < n)
        ((float4*)out)[r1] = make_float4(f2lo(RH[0]), f2hi(RH[0]), f2lo(RH[1]), f2hi(RH[1]));
}

// ---------------- launch -----------------------------------------------------
extern "C" void kernel_launch(void* const* d_in, const int* in_sizes, int n_in,
                              void* d_out, int out_size)
{
    const float* obs   = (const float*)d_in[0];
    const float* wq0   = (const float*)d_in[1];
    const float* wak0  = (const float*)d_in[2];
    const float* wav0  = (const float*)d_in[3];
    const float* wok0  = (const float*)d_in[4];
    const float* wov0  = (const float*)d_in[5];
    const float* apw0  = (const float*)d_in[6];
    const float* apb0  = (const float*)d_in[7];
    const float* opw0  = (const float*)d_in[8];
    const float* opb0  = (const float*)d_in[9];
    const float* fpw0  = (const float*)d_in[10];
    const float* fpb0  = (const float*)d_in[11];
    const float* ca0   = (const float*)d_in[12];
    const float* co0   = (const float*)d_in[13];
    const float* wq1   = (const float*)d_in[14];
    const float* wak1  = (const float*)d_in[15];
    const float* wav1  = (const float*)d_in[16];
    const float* wok1  = (const float*)d_in[17];
    const float* wov1  = (const float*)d_in[18];
    const float* apw1  = (const float*)d_in[19];
    const float* apb1  = (const float*)d_in[20];
    const float* opw1  = (const float*)d_in[21];
    const float* opb1  = (const float*)d_in[22];
    const float* fpw1  = (const float*)d_in[23];
    const float* fpb1  = (const float*)d_in[24];
    const float* ca1   = (const float*)d_in[25];
    const float* co1   = (const float*)d_in[26];
    const float* headw = (const float*)d_in[27];
    const float* headb = (const float*)d_in[28];

    int n = in_sizes[0] / 37;

    pk<<<93, 512>>>(wq0, wak0, wok0, wq1, wak1, wok1,
                    wav0, apw0, wov0, opw0, wav1, apw1, wov1, opw1,
                    fpw0, fpw1, fpb0, apb0, opb0, fpb1, apb1, opb1,
                    headw, headb);

    cudaFuncSetAttribute(actor_main, cudaFuncAttributeMaxDynamicSharedMemorySize, SM_TOTAL);

    int grid = (n + MROWS - 1) / MROWS;

    cudaLaunchConfig_t cfg = {};
    cfg.gridDim  = dim3((unsigned)grid, 1, 1);
    cfg.blockDim = dim3(MT, 1, 1);
    cfg.dynamicSmemBytes = SM_TOTAL;
    cfg.stream = 0;
    cudaLaunchAttribute attrs[1];
    attrs[0].id = cudaLaunchAttributeProgrammaticStreamSerialization;
    attrs[0].val.programmaticStreamSerializationAllowed = 1;
    cfg.attrs = attrs;
    cfg.numAttrs = 1;

    cudaLaunchKernelEx(&cfg, actor_main, obs, ca0, co0, ca1, co1, (float*)d_out, n);
}